// round 13
// baseline (speedup 1.0000x reference)
#include <cuda_runtime.h>
#include <cuda_bf16.h>
#include <cuda_fp16.h>
#include <mma.h>
#include <cstdint>
#include <math.h>

using namespace nvcuda;

#define Bb 256
#define Ll 256
#define Dd 768
#define Hh 1024
#define Tt 32
#define KV (3*Dd)   // 2304
#define Gg (4*Hh)   // 4096
#define NL (3*Ll)   // 768
#define KCH 64      // K elems per smem chunk
#define LDS 72      // padded smem stride (elems), 144 B
#define BH (Bb*Hh)

// GEMM tile: 64x128 CTA, 128 threads (4 warps 2x2), warp tile 32x64 (FM=2, FN=4)
#define BMg 64
#define BNg 128
#define SSg ((2*BMg + 2*BNg) * LDS * 2)     // 55296 B per stage
#define AOFFg (BMg * LDS * 2)                // 9216
#define BOFFg (2 * BMg * LDS * 2)            // 18432
#define BLOFFg (BOFFg + BNg * LDS * 2)       // 36864
#define SMEMg (2 * SSg)                      // 110592

// ======================= device scratch =======================
__device__ float g_c[BH];
__device__ float g_attP[4*Bb*NL];                  // logits split-K-4 partials
__device__ float g_gates0[Bb*Gg], g_gates1[Bb*Gg]; // hh split-K partials (gate-interleaved)
__device__ float g_ih0[Bb*Gg], g_ih1[Bb*Gg];       // ih split-K partials (gate-interleaved)
__device__ float g_biasG[Gg];             // reordered: [unit*4+gate]
__device__ float g_biasA[NL];
__device__ int   g_cnt[128];              // fixup counters per output tile
__device__ __align__(16) __half g_xh[Bb*Ll*Dd];    // x in fp16
// h double-buffered by step parity: readers use [par], fixup LSTM writes [par^1]
__device__ __align__(16) __nv_bfloat16 g_hh_[2*BH], g_hl_[2*BH];
__device__ __align__(16) __nv_bfloat16 g_vh_[Bb*KV], g_vl_[Bb*KV];
__device__ __align__(16) __nv_bfloat16 g_Wah[NL*Hh],  g_Wal[NL*Hh];
__device__ __align__(16) __nv_bfloat16 g_Wihh[Gg*KV], g_Wihl[Gg*KV];   // rows reordered
__device__ __align__(16) __nv_bfloat16 g_Whhh[Gg*Hh], g_Whhl[Gg*Hh];   // rows reordered

__device__ __forceinline__ void split2(float a, __nv_bfloat16* hi, __nv_bfloat16* lo) {
    __nv_bfloat16 h = __float2bfloat16_rn(a);
    *hi = h;
    *lo = __float2bfloat16_rn(a - __bfloat162float(h));
}
__device__ __forceinline__ uint32_t smem_u32(const void* p) {
    uint32_t a;
    asm("{ .reg .u64 t; cvta.to.shared.u64 t, %1; cvt.u32.u64 %0, t; }" : "=r"(a) : "l"(p));
    return a;
}
__device__ __forceinline__ void cp16(uint32_t s, const void* g) {
    asm volatile("cp.async.cg.shared.global [%0], [%1], 16;" :: "r"(s), "l"(g));
}
#define CP_COMMIT() asm volatile("cp.async.commit_group;" ::: "memory")
#define CP_WAIT(n)  asm volatile("cp.async.wait_group %0;" :: "n"(n) : "memory")
__device__ __forceinline__ float sigmoidf_(float x) { return 1.0f / (1.0f + expf(-x)); }

// ======================= prep kernels =======================
__global__ void split_kernel(const float* __restrict__ src, __nv_bfloat16* __restrict__ hi,
                             __nv_bfloat16* __restrict__ lo, int n) {
    for (int i = blockIdx.x * blockDim.x + threadIdx.x; i < n; i += gridDim.x * blockDim.x)
        split2(src[i], &hi[i], &lo[i]);
}

__global__ void x2h_kernel(const float* __restrict__ x) {
    __half2* dst = (__half2*)g_xh;
    const float2* src = (const float2*)x;
    int n2 = Bb*Ll*Dd/2;
    for (int i = blockIdx.x * blockDim.x + threadIdx.x; i < n2; i += gridDim.x * blockDim.x) {
        float2 f = src[i];
        dst[i] = __floats2half2_rn(f.x, f.y);
    }
}

// split + gate-interleave row reorder: orig row r = gate*1024+unit -> r' = unit*4+gate
__global__ void split_reorder_kernel(const float* __restrict__ src, __nv_bfloat16* __restrict__ hi,
                                     __nv_bfloat16* __restrict__ lo, int K, int n) {
    for (int i = blockIdx.x * blockDim.x + threadIdx.x; i < n; i += gridDim.x * blockDim.x) {
        int r = i / K, k = i - r * K;
        int gate = r >> 10, unit = r & 1023;
        size_t dst = (size_t)(unit * 4 + gate) * K + k;
        split2(src[i], &hi[dst], &lo[dst]);
    }
}

__global__ void bias_prep_kernel(const float* __restrict__ b_ih, const float* __restrict__ b_hh,
                                 const float* __restrict__ b1, const float* __restrict__ b2,
                                 const float* __restrict__ b3) {
    int j = blockIdx.x * blockDim.x + threadIdx.x;
    if (j < Gg) {
        int gate = j >> 10, unit = j & 1023;
        g_biasG[unit * 4 + gate] = b_ih[j] + b_hh[j];
    }
    if (j < NL) g_biasA[j] = (j < Ll) ? b1[j] : (j < 2*Ll) ? b2[j - Ll] : b3[j - 2*Ll];
    if (j < 128) g_cnt[j] = 0;
}

__global__ void init_kernel(const float* __restrict__ h0, const float* __restrict__ c0) {
    int i = blockIdx.x * blockDim.x + threadIdx.x;
    if (i < BH) { split2(h0[i], &g_hh_[i], &g_hl_[i]); g_c[i] = c0[i]; }
}

// ======================= GEMM mainloop core (64x128 tile, 128 thr, warps 2x2) ===========
template <int NCH>
__device__ __forceinline__ void gemm_core(
    char* smem, uint32_t sb, int tid,
    const __nv_bfloat16* __restrict__ Ah, const __nv_bfloat16* __restrict__ Al,
    const __nv_bfloat16* __restrict__ Wh, const __nv_bfloat16* __restrict__ Wl,
    int K, int row0, int col0,
    wmma::fragment<wmma::accumulator, 16, 16, 16, float> (&acc)[2][4],
    int wm, int wn)
{
    auto load_chunk = [&](int kc, int s) {
        const int ka = kc * KCH;
        const uint32_t st = sb + s * SSg;
        #pragma unroll
        for (int it = 0; it < 4; it++) {                 // A: 64 rows
            int idx = tid + it * 128, r = idx >> 3, q = idx & 7;
            size_t src = (size_t)(row0 + r) * K + ka + q * 8;
            uint32_t off = r * (LDS*2) + q * 16;
            cp16(st + off, Ah + src);
            cp16(st + AOFFg + off, Al + src);
        }
        #pragma unroll
        for (int it = 0; it < 8; it++) {                 // B: 128 rows
            int idx = tid + it * 128, r = idx >> 3, q = idx & 7;
            size_t src = (size_t)(col0 + r) * K + ka + q * 8;
            uint32_t off = r * (LDS*2) + q * 16;
            cp16(st + BOFFg + off, Wh + src);
            cp16(st + BLOFFg + off, Wl + src);
        }
    };

    load_chunk(0, 0); CP_COMMIT();
    for (int kc = 0; kc < NCH; kc++) {
        if (kc + 1 < NCH) { load_chunk(kc + 1, (kc + 1) & 1); CP_COMMIT(); CP_WAIT(1); }
        else              { CP_WAIT(0); }
        __syncthreads();
        const char* st = smem + (kc & 1) * SSg;
        const __nv_bfloat16* pAh = (const __nv_bfloat16*)st;
        const __nv_bfloat16* pAl = (const __nv_bfloat16*)(st + AOFFg);
        const __nv_bfloat16* pBh = (const __nv_bfloat16*)(st + BOFFg);
        const __nv_bfloat16* pBl = (const __nv_bfloat16*)(st + BLOFFg);
        #pragma unroll
        for (int k16 = 0; k16 < KCH/16; k16++) {
            const int kk = k16 * 16;
            wmma::fragment<wmma::matrix_a, 16, 16, 16, __nv_bfloat16, wmma::row_major> ah[2], al[2];
            #pragma unroll
            for (int i = 0; i < 2; i++) {
                int rr = wm * 32 + i * 16;
                wmma::load_matrix_sync(ah[i], pAh + rr * LDS + kk, LDS);
                wmma::load_matrix_sync(al[i], pAl + rr * LDS + kk, LDS);
            }
            #pragma unroll
            for (int j = 0; j < 4; j++) {
                int cc = wn * 64 + j * 16;
                wmma::fragment<wmma::matrix_b, 16, 16, 16, __nv_bfloat16, wmma::col_major> bh, bl;
                wmma::load_matrix_sync(bh, pBh + cc * LDS + kk, LDS);
                wmma::load_matrix_sync(bl, pBl + cc * LDS + kk, LDS);
                #pragma unroll
                for (int i = 0; i < 2; i++) {
                    wmma::mma_sync(acc[i][j], ah[i], bh, acc[i][j]);
                    wmma::mma_sync(acc[i][j], ah[i], bl, acc[i][j]);
                    wmma::mma_sync(acc[i][j], al[i], bh, acc[i][j]);
                }
            }
        }
        __syncthreads();
    }
}

// ======================= logits, split-K 4-way =======================
// 96 CTAs x 128 thr: quarter q = bid/24, tile tt = bid%24 (4x6). K=256 per quarter.
__global__ void __launch_bounds__(128) logits_kernel(int par) {
    extern __shared__ __align__(16) char smem[];
    const uint32_t sb = smem_u32(smem);
    const int tid = threadIdx.x, wid = tid >> 5, wm = wid >> 1, wn = wid & 1;
    const int bid = blockIdx.x;
    const int quar = bid / 24, tt = bid % 24;
    const int m_t = tt & 3, n_t = tt >> 2;      // n_t 0..5
    const int row0 = m_t * BMg, col0 = n_t * BNg;
    const int ko = quar * 256;
    float* C = g_attP + quar * (Bb * NL);
    const __nv_bfloat16* hh = g_hh_ + (size_t)par * BH;
    const __nv_bfloat16* hl = g_hl_ + (size_t)par * BH;

    wmma::fragment<wmma::accumulator, 16, 16, 16, float> acc[2][4];
    #pragma unroll
    for (int i = 0; i < 2; i++) for (int j = 0; j < 4; j++) wmma::fill_fragment(acc[i][j], 0.0f);

    gemm_core<4>(smem, sb, tid, hh + ko, hl + ko, g_Wah + ko, g_Wal + ko,
                 Hh, row0, col0, acc, wm, wn);

    #pragma unroll
    for (int i = 0; i < 2; i++)
        #pragma unroll
        for (int j = 0; j < 4; j++) {
            int row = row0 + wm * 32 + i * 16;
            int col = col0 + wn * 64 + j * 16;
            wmma::store_matrix_sync(&C[(size_t)row * NL + col], acc[i][j], NL, wmma::mem_row_major);
        }
}

// ======================= hh + ih GEMM, split-K 2-way each, + fixup LSTM ==============
// 512 CTAs x 128 thr: bid<256 -> ih tile (K=1152 halves); else hh tile (K=512 halves).
// 4 partial-CTAs per output tile; 4th arrival runs LSTM epilogue.
// h is double-buffered: GEMMs read buffer par, LSTM epilogue writes buffer par^1.
__global__ void __launch_bounds__(128) hhih_kernel(float* __restrict__ out, int t_step) {
    extern __shared__ __align__(16) char smem[];
    const uint32_t sb = smem_u32(smem);
    const int tid = threadIdx.x, wid = tid >> 5, wm = wid >> 1, wn = wid & 1;
    const int bid = blockIdx.x;
    const int par = t_step & 1;
    const bool isIH = bid < 256;
    const int b2 = isIH ? bid : bid - 256;
    const int half = b2 >> 7, tt = b2 & 127;
    const int m_t = tt & 3, n_t = tt >> 2;      // n_t 0..31
    const int row0 = m_t * BMg, col0 = n_t * BNg;

    wmma::fragment<wmma::accumulator, 16, 16, 16, float> acc[2][4];
    #pragma unroll
    for (int i = 0; i < 2; i++) for (int j = 0; j < 4; j++) wmma::fill_fragment(acc[i][j], 0.0f);

    float* C;
    if (isIH) {
        const int ko = half * 1152;
        C = half ? g_ih1 : g_ih0;
        gemm_core<18>(smem, sb, tid, g_vh_ + ko, g_vl_ + ko, g_Wihh + ko, g_Wihl + ko,
                      KV, row0, col0, acc, wm, wn);
    } else {
        const int ko = half * 512;
        C = half ? g_gates1 : g_gates0;
        const __nv_bfloat16* hh = g_hh_ + (size_t)par * BH;
        const __nv_bfloat16* hl = g_hl_ + (size_t)par * BH;
        gemm_core<8>(smem, sb, tid, hh + ko, hl + ko, g_Whhh + ko, g_Whhl + ko,
                     Hh, row0, col0, acc, wm, wn);
    }

    #pragma unroll
    for (int i = 0; i < 2; i++)
        #pragma unroll
        for (int j = 0; j < 4; j++) {
            int row = row0 + wm * 32 + i * 16;
            int col = col0 + wn * 64 + j * 16;
            wmma::store_matrix_sync(&C[(size_t)row * Gg + col], acc[i][j], Gg, wmma::mem_row_major);
        }

    // ---- split-K fixup: 4th CTA for this tile does the LSTM epilogue ----
    __syncthreads();
    __shared__ int sWin;
    if (tid == 0) {
        __threadfence();
        int old = atomicAdd(&g_cnt[m_t * 32 + n_t], 1);
        int win = (old == 3);
        if (win) g_cnt[m_t * 32 + n_t] = 0;     // reset for next step
        sWin = win;
    }
    __syncthreads();
    if (!sWin) return;
    __threadfence();

    __nv_bfloat16* nhh = g_hh_ + (size_t)(par ^ 1) * BH;
    __nv_bfloat16* nhl = g_hl_ + (size_t)(par ^ 1) * BH;
    const int unit0 = n_t * 32;
    #pragma unroll
    for (int it = 0; it < 16; it++) {
        int idx = tid + it * 128;               // 0..2047
        int r = idx >> 5, u = idx & 31;
        int row = row0 + r;
        size_t go = (size_t)row * Gg + n_t * 128 + u * 4;
        float4 a0 = *(const float4*)&g_ih0[go];
        float4 a1 = *(const float4*)&g_ih1[go];
        float4 p0 = *(const float4*)&g_gates0[go];
        float4 p1 = *(const float4*)&g_gates1[go];
        float4 bv = *(const float4*)&g_biasG[n_t * 128 + u * 4];
        float ig = a0.x + a1.x + p0.x + p1.x + bv.x;
        float fg = a0.y + a1.y + p0.y + p1.y + bv.y;
        float gg = a0.z + a1.z + p0.z + p1.z + bv.z;
        float og = a0.w + a1.w + p0.w + p1.w + bv.w;
        int unit = unit0 + u;
        int ci = row * Hh + unit;
        float c = g_c[ci];
        float cn = sigmoidf_(fg) * c + sigmoidf_(ig) * tanhf(gg);
        float hn = sigmoidf_(og) * tanhf(cn);
        g_c[ci] = cn;
        split2(hn, &nhh[ci], &nhl[ci]);
        out[((size_t)row * Tt + t_step) * Hh + unit] = hn;
    }
}

// ======================= fused softmax + attention-value (fp16 x), D-split 2-way ========
// 512 CTAs x 384 thr: bid = b*2 + half. Each CTA handles D columns [half*384, +384).
__global__ void __launch_bounds__(384, 4) attnv_kernel() {
    const int bid = blockIdx.x;
    const int b = bid >> 1, half = bid & 1;
    const int tid = threadIdx.x;

    __shared__ float a[3][Ll];
    __shared__ float2 part[3][2][192];
    __shared__ float red[3][8];

    // --- softmax (threads 0..255), logits = sum of 4 split-K partials + bias ---
    float e[3], v[3];
    if (tid < 256) {
        #pragma unroll
        for (int h = 0; h < 3; h++) {
            int o = b * NL + h * 256 + tid;
            v[h] = g_attP[o] + g_attP[Bb*NL + o] + g_attP[2*Bb*NL + o] + g_attP[3*Bb*NL + o]
                 + g_biasA[h * 256 + tid];
        }
        int w8 = tid >> 5;
        #pragma unroll
        for (int h = 0; h < 3; h++) {
            float m = v[h];
            #pragma unroll
            for (int o = 16; o; o >>= 1) m = fmaxf(m, __shfl_xor_sync(0xffffffffu, m, o));
            if ((tid & 31) == 0) red[h][w8] = m;
        }
    }
    __syncthreads();
    if (tid < 256) {
        int w8 = tid >> 5;
        #pragma unroll
        for (int h = 0; h < 3; h++) {
            float mm = red[h][0];
            #pragma unroll
            for (int q = 1; q < 8; q++) mm = fmaxf(mm, red[h][q]);
            e[h] = expf(v[h] - mm);
        }
        __syncthreads();
        #pragma unroll
        for (int h = 0; h < 3; h++) {
            float s = e[h];
            #pragma unroll
            for (int o = 16; o; o >>= 1) s += __shfl_xor_sync(0xffffffffu, s, o);
            if ((tid & 31) == 0) red[h][w8] = s;
        }
    } else {
        __syncthreads();
    }
    __syncthreads();
    if (tid < 256) {
        #pragma unroll
        for (int h = 0; h < 3; h++) {
            float s = red[h][0];
            #pragma unroll
            for (int q = 1; q < 8; q++) s += red[h][q];
            a[h][tid] = e[h] / s;
        }
    }
    __syncthreads();

    // --- value gather over this CTA's D-half: 192 half2 cols, L split 2-way ---
    const int ty = tid / 192, tx = tid % 192;     // ty 0..1
    const __half2* xb2 = (const __half2*)g_xh + (size_t)b * Ll * (Dd/2) + half * 192;
    float2 s0 = {0,0}, s1 = {0,0}, s2 = {0,0};
    const int l0 = ty * 128;
    #pragma unroll 8
    for (int l = l0; l < l0 + 128; l++) {
        float w0 = a[0][l], w1 = a[1][l], w2 = a[2][l];
        float2 xv = __half22float2(xb2[(size_t)l * 384 + tx]);
        s0.x += w0*xv.x; s0.y += w0*xv.y;
        s1.x += w1*xv.x; s1.y += w1*xv.y;
        s2.x += w2*xv.x; s2.y += w2*xv.y;
    }
    part[0][ty][tx] = s0; part[1][ty][tx] = s1; part[2][ty][tx] = s2;
    __syncthreads();

    // reduce + split-write: 3 heads x 192 float2 = 576 items over 384 threads
    for (int sIdx = tid; sIdx < 576; sIdx += 384) {
        int h = sIdx / 192, c = sIdx % 192;
        float2 r0 = part[h][0][c], r1 = part[h][1][c];
        float rx = r0.x + r1.x, ry = r0.y + r1.y;
        size_t o = (size_t)b * KV + h * Dd + half * 384 + c * 2;
        split2(rx, &g_vh_[o],     &g_vl_[o]);
        split2(ry, &g_vh_[o + 1], &g_vl_[o + 1]);
    }
}

// ======================= driver (single stream, graph-safe) =======================
extern "C" void kernel_launch(void* const* d_in, const int* in_sizes, int n_in,
                              void* d_out, int out_size) {
    (void)in_sizes; (void)n_in; (void)out_size;
    const float* x    = (const float*)d_in[0];
    const float* h0   = (const float*)d_in[1];
    const float* c0   = (const float*)d_in[2];
    const float* W1   = (const float*)d_in[3];
    const float* b1   = (const float*)d_in[4];
    const float* W2   = (const float*)d_in[5];
    const float* b2   = (const float*)d_in[6];
    const float* W3   = (const float*)d_in[7];
    const float* b3   = (const float*)d_in[8];
    const float* W_ih = (const float*)d_in[9];
    const float* W_hh = (const float*)d_in[10];
    const float* b_ih = (const float*)d_in[11];
    const float* b_hh = (const float*)d_in[12];
    float* out = (float*)d_out;

    cudaFuncSetAttribute(logits_kernel, cudaFuncAttributeMaxDynamicSharedMemorySize, SMEMg);
    cudaFuncSetAttribute(hhih_kernel,   cudaFuncAttributeMaxDynamicSharedMemorySize, SMEMg);

    __nv_bfloat16 *wah, *wal, *wihh, *wihl, *whhh, *whhl;
    cudaGetSymbolAddress((void**)&wah,  g_Wah);
    cudaGetSymbolAddress((void**)&wal,  g_Wal);
    cudaGetSymbolAddress((void**)&wihh, g_Wihh);
    cudaGetSymbolAddress((void**)&wihl, g_Wihl);
    cudaGetSymbolAddress((void**)&whhh, g_Whhh);
    cudaGetSymbolAddress((void**)&whhl, g_Whhl);

    x2h_kernel<<<2048, 256>>>(x);
    split_reorder_kernel<<<4096, 256>>>(W_ih, wihh, wihl, KV, Gg*KV);
    split_reorder_kernel<<<4096, 256>>>(W_hh, whhh, whhl, Hh, Gg*Hh);
    split_kernel<<<1024, 256>>>(W1, wah,           wal,           Ll*Hh);
    split_kernel<<<1024, 256>>>(W2, wah + Ll*Hh,   wal + Ll*Hh,   Ll*Hh);
    split_kernel<<<1024, 256>>>(W3, wah + 2*Ll*Hh, wal + 2*Ll*Hh, Ll*Hh);
    bias_prep_kernel<<<16, 256>>>(b_ih, b_hh, b1, b2, b3);
    init_kernel<<<(BH + 255)/256, 256>>>(h0, c0);

    for (int t = 0; t < Tt; t++) {
        logits_kernel<<<96, 128, SMEMg>>>(t & 1);          // split-K-4 logits partials
        attnv_kernel<<<512, 384>>>();                      // softmax + fp16 value gather
        hhih_kernel<<<512, 128, SMEMg>>>(out, t);          // hh+ih GEMMs + fixup LSTM
    }
}

// round 14
// speedup vs baseline: 1.3562x; 1.3562x over previous
#include <cuda_runtime.h>
#include <cuda_bf16.h>
#include <cuda_fp16.h>
#include <mma.h>
#include <cstdint>
#include <math.h>

using namespace nvcuda;

#define Bb 256
#define Ll 256
#define Dd 768
#define Hh 1024
#define Tt 32
#define KV (3*Dd)   // 2304
#define KA (KV+Hh)  // 3328 concat [v|h]
#define Gg (4*Hh)   // 4096
#define NL (3*Ll)   // 768
#define KCH 64      // K elems per smem chunk
#define LDS 72      // padded smem stride (elems), 144 B
#define BH (Bb*Hh)
#define BKA (Bb*KA)

// GEMM tile: 64x128 CTA, 128 threads (4 warps 2x2), warp tile 32x64 (FM=2, FN=4)
// 2-term fp16: A single, W hi+lo.
#define BMg 64
#define BNg 128
#define SS2 ((BMg + 2*BNg) * LDS * 2)       // 46080 B per stage
#define BOFF2 (BMg * LDS * 2)                // 9216
#define BLOFF2 (BOFF2 + BNg * LDS * 2)       // 27648
#define SMEM2 (2 * SS2)                      // 92160

// ======================= device scratch =======================
__device__ float g_c[BH];
__device__ float g_attP[4*Bb*NL];                  // logits split-K-4 partials
__device__ float g_ih0[Bb*Gg], g_ih1[Bb*Gg];       // gates split-K partials (gate-interleaved)
__device__ float g_biasG[Gg];             // reordered: [unit*4+gate]
__device__ float g_biasA[NL];
__device__ __align__(16) __half g_xh[Bb*Ll*Dd];    // x in fp16
// A = [v | h], fp16, double-buffered by step parity
__device__ __align__(16) __half g_A[2*BKA];
__device__ __align__(16) __half g_Wah[NL*Hh],  g_Wal[NL*Hh];     // logits weights hi/lo
__device__ __align__(16) __half g_Wh[(size_t)Gg*KA], g_Wl[(size_t)Gg*KA];  // [Wih|Whh], rows gate-interleaved

__device__ __forceinline__ void split2h(float a, __half* hi, __half* lo) {
    __half h = __float2half_rn(a);
    *hi = h;
    *lo = __float2half_rn(a - __half2float(h));
}
__device__ __forceinline__ uint32_t smem_u32(const void* p) {
    uint32_t a;
    asm("{ .reg .u64 t; cvta.to.shared.u64 t, %1; cvt.u32.u64 %0, t; }" : "=r"(a) : "l"(p));
    return a;
}
__device__ __forceinline__ void cp16(uint32_t s, const void* g) {
    asm volatile("cp.async.cg.shared.global [%0], [%1], 16;" :: "r"(s), "l"(g));
}
#define CP_COMMIT() asm volatile("cp.async.commit_group;" ::: "memory")
#define CP_WAIT(n)  asm volatile("cp.async.wait_group %0;" :: "n"(n) : "memory")
__device__ __forceinline__ float sigmoidf_(float x) { return 1.0f / (1.0f + expf(-x)); }

// ======================= prep kernels =======================
__global__ void split_h_kernel(const float* __restrict__ src, __half* __restrict__ hi,
                               __half* __restrict__ lo, int n) {
    for (int i = blockIdx.x * blockDim.x + threadIdx.x; i < n; i += gridDim.x * blockDim.x)
        split2h(src[i], &hi[i], &lo[i]);
}

__global__ void x2h_kernel(const float* __restrict__ x) {
    __half2* dst = (__half2*)g_xh;
    const float2* src = (const float2*)x;
    int n2 = Bb*Ll*Dd/2;
    for (int i = blockIdx.x * blockDim.x + threadIdx.x; i < n2; i += gridDim.x * blockDim.x) {
        float2 f = src[i];
        dst[i] = __floats2half2_rn(f.x, f.y);
    }
}

// W_ih [4096 x 2304]: row gate*1024+unit -> row' unit*4+gate, cols [0, 2304)
__global__ void reorder_ih_kernel(const float* __restrict__ src) {
    for (int i = blockIdx.x * blockDim.x + threadIdx.x; i < Gg*KV; i += gridDim.x * blockDim.x) {
        int r = i / KV, k = i - r * KV;
        int gate = r >> 10, unit = r & 1023;
        size_t dst = (size_t)(unit * 4 + gate) * KA + k;
        split2h(src[i], &g_Wh[dst], &g_Wl[dst]);
    }
}
// W_hh [4096 x 1024]: cols [2304, 3328)
__global__ void reorder_hh_kernel(const float* __restrict__ src) {
    for (int i = blockIdx.x * blockDim.x + threadIdx.x; i < Gg*Hh; i += gridDim.x * blockDim.x) {
        int r = i / Hh, k = i - r * Hh;
        int gate = r >> 10, unit = r & 1023;
        size_t dst = (size_t)(unit * 4 + gate) * KA + KV + k;
        split2h(src[i], &g_Wh[dst], &g_Wl[dst]);
    }
}

__global__ void bias_prep_kernel(const float* __restrict__ b_ih, const float* __restrict__ b_hh,
                                 const float* __restrict__ b1, const float* __restrict__ b2,
                                 const float* __restrict__ b3) {
    int j = blockIdx.x * blockDim.x + threadIdx.x;
    if (j < Gg) {
        int gate = j >> 10, unit = j & 1023;
        g_biasG[unit * 4 + gate] = b_ih[j] + b_hh[j];
    }
    if (j < NL) g_biasA[j] = (j < Ll) ? b1[j] : (j < 2*Ll) ? b2[j - Ll] : b3[j - 2*Ll];
}

__global__ void init_kernel(const float* __restrict__ h0, const float* __restrict__ c0) {
    int i = blockIdx.x * blockDim.x + threadIdx.x;
    if (i < BH) {
        int row = i >> 10, u = i & 1023;
        g_A[(size_t)row * KA + KV + u] = __float2half_rn(h0[i]);   // buffer 0 h-part
        g_c[i] = c0[i];
    }
}

// ======================= 2-term fp16 GEMM core (64x128 tile, 128 thr, warps 2x2) ========
// acc[2][4] = A[row0:+64, :] @ (Wh+Wl)[col0:+128, :]^T over NCH chunks of 64
template <int NCH>
__device__ __forceinline__ void gemm_core2(
    char* smem, uint32_t sb, int tid,
    const __half* __restrict__ A,
    const __half* __restrict__ Wh, const __half* __restrict__ Wl,
    int lda, int ldb, int row0, int col0,
    wmma::fragment<wmma::accumulator, 16, 16, 16, float> (&acc)[2][4],
    int wm, int wn)
{
    auto load_chunk = [&](int kc, int s) {
        const int ka = kc * KCH;
        const uint32_t st = sb + s * SS2;
        #pragma unroll
        for (int it = 0; it < 4; it++) {                 // A: 64 rows, single
            int idx = tid + it * 128, r = idx >> 3, q = idx & 7;
            size_t src = (size_t)(row0 + r) * lda + ka + q * 8;
            uint32_t off = r * (LDS*2) + q * 16;
            cp16(st + off, A + src);
        }
        #pragma unroll
        for (int it = 0; it < 8; it++) {                 // B: 128 rows, hi+lo
            int idx = tid + it * 128, r = idx >> 3, q = idx & 7;
            size_t src = (size_t)(col0 + r) * ldb + ka + q * 8;
            uint32_t off = r * (LDS*2) + q * 16;
            cp16(st + BOFF2 + off, Wh + src);
            cp16(st + BLOFF2 + off, Wl + src);
        }
    };

    load_chunk(0, 0); CP_COMMIT();
    for (int kc = 0; kc < NCH; kc++) {
        if (kc + 1 < NCH) { load_chunk(kc + 1, (kc + 1) & 1); CP_COMMIT(); CP_WAIT(1); }
        else              { CP_WAIT(0); }
        __syncthreads();
        const char* st = smem + (kc & 1) * SS2;
        const __half* pA  = (const __half*)st;
        const __half* pBh = (const __half*)(st + BOFF2);
        const __half* pBl = (const __half*)(st + BLOFF2);
        #pragma unroll
        for (int k16 = 0; k16 < KCH/16; k16++) {
            const int kk = k16 * 16;
            wmma::fragment<wmma::matrix_a, 16, 16, 16, __half, wmma::row_major> af[2];
            #pragma unroll
            for (int i = 0; i < 2; i++)
                wmma::load_matrix_sync(af[i], pA + (wm * 32 + i * 16) * LDS + kk, LDS);
            #pragma unroll
            for (int j = 0; j < 4; j++) {
                int cc = wn * 64 + j * 16;
                wmma::fragment<wmma::matrix_b, 16, 16, 16, __half, wmma::col_major> bh, bl;
                wmma::load_matrix_sync(bh, pBh + cc * LDS + kk, LDS);
                wmma::load_matrix_sync(bl, pBl + cc * LDS + kk, LDS);
                #pragma unroll
                for (int i = 0; i < 2; i++) {
                    wmma::mma_sync(acc[i][j], af[i], bh, acc[i][j]);
                    wmma::mma_sync(acc[i][j], af[i], bl, acc[i][j]);
                }
            }
        }
        __syncthreads();
    }
}

// ======================= logits, split-K 4-way =======================
// 96 CTAs x 128 thr: quarter = bid/24, tile = bid%24 (4m x 6n). K=256 per quarter.
__global__ void __launch_bounds__(128) logits_kernel(int par) {
    extern __shared__ __align__(16) char smem[];
    const uint32_t sb = smem_u32(smem);
    const int tid = threadIdx.x, wid = tid >> 5, wm = wid >> 1, wn = wid & 1;
    const int bid = blockIdx.x;
    const int quar = bid / 24, tt = bid % 24;
    const int m_t = tt & 3, n_t = tt >> 2;      // n_t 0..5
    const int row0 = m_t * BMg, col0 = n_t * BNg;
    const int ko = quar * 256;
    float* C = g_attP + quar * (Bb * NL);
    const __half* A = g_A + (size_t)par * BKA + KV;  // h part, row stride KA

    wmma::fragment<wmma::accumulator, 16, 16, 16, float> acc[2][4];
    #pragma unroll
    for (int i = 0; i < 2; i++) for (int j = 0; j < 4; j++) wmma::fill_fragment(acc[i][j], 0.0f);

    gemm_core2<4>(smem, sb, tid, A + ko, g_Wah + ko, g_Wal + ko,
                  KA, Hh, row0, col0, acc, wm, wn);

    #pragma unroll
    for (int i = 0; i < 2; i++)
        #pragma unroll
        for (int j = 0; j < 4; j++) {
            int row = row0 + wm * 32 + i * 16;
            int col = col0 + wn * 64 + j * 16;
            wmma::store_matrix_sync(&C[(size_t)row * NL + col], acc[i][j], NL, wmma::mem_row_major);
        }
}

// ======================= gates GEMM: [v|h] @ [Wih|Whh]^T, split-K 2-way ================
// 256 CTAs x 128 thr: half = bid>>7, tile (4m x 32n). K=3328 -> 26 chunks per half.
__global__ void __launch_bounds__(128) gates_kernel(int par) {
    extern __shared__ __align__(16) char smem[];
    const uint32_t sb = smem_u32(smem);
    const int tid = threadIdx.x, wid = tid >> 5, wm = wid >> 1, wn = wid & 1;
    const int bid = blockIdx.x;
    const int half = bid >> 7, tt = bid & 127;
    const int m_t = tt & 3, n_t = tt >> 2;      // n_t 0..31
    const int row0 = m_t * BMg, col0 = n_t * BNg;
    const int ko = half * 1664;                 // 26 * 64
    float* C = half ? g_ih1 : g_ih0;
    const __half* A = g_A + (size_t)par * BKA;

    wmma::fragment<wmma::accumulator, 16, 16, 16, float> acc[2][4];
    #pragma unroll
    for (int i = 0; i < 2; i++) for (int j = 0; j < 4; j++) wmma::fill_fragment(acc[i][j], 0.0f);

    gemm_core2<26>(smem, sb, tid, A + ko, g_Wh + ko, g_Wl + ko,
                   KA, KA, row0, col0, acc, wm, wn);

    #pragma unroll
    for (int i = 0; i < 2; i++)
        #pragma unroll
        for (int j = 0; j < 4; j++) {
            int row = row0 + wm * 32 + i * 16;
            int col = col0 + wn * 64 + j * 16;
            wmma::store_matrix_sync(&C[(size_t)row * Gg + col], acc[i][j], Gg, wmma::mem_row_major);
        }
}

// ======================= LSTM pointwise: sum 2 partials + bias =======================
__global__ void __launch_bounds__(256) lstm_kernel(float* __restrict__ out, int t_step) {
    int idx = blockIdx.x * blockDim.x + threadIdx.x;  // B*H
    int row = idx >> 10, u = idx & 1023;
    const int par = t_step & 1;
    size_t go = (size_t)row * Gg + u * 4;
    float4 a0 = *(const float4*)&g_ih0[go];
    float4 a1 = *(const float4*)&g_ih1[go];
    float4 bv = *(const float4*)&g_biasG[u * 4];
    float ig = a0.x + a1.x + bv.x;
    float fg = a0.y + a1.y + bv.y;
    float gg = a0.z + a1.z + bv.z;
    float og = a0.w + a1.w + bv.w;
    float c = g_c[idx];
    float cn = sigmoidf_(fg) * c + sigmoidf_(ig) * tanhf(gg);
    float hn = sigmoidf_(og) * tanhf(cn);
    g_c[idx] = cn;
    g_A[(size_t)(par ^ 1) * BKA + (size_t)row * KA + KV + u] = __float2half_rn(hn);
    out[((size_t)row * Tt + t_step) * Hh + u] = hn;
}

// ======================= fused softmax + attention-value (fp16 x), D-split 2-way ========
// 512 CTAs x 384 thr: bid = b*2 + half. Writes v (fp16) into g_A[par] v-part.
__global__ void __launch_bounds__(384, 4) attnv_kernel(int par) {
    const int bid = blockIdx.x;
    const int b = bid >> 1, half = bid & 1;
    const int tid = threadIdx.x;

    __shared__ float a[3][Ll];
    __shared__ float2 part[3][2][192];
    __shared__ float red[3][8];

    // --- softmax (threads 0..255), logits = sum of 4 split-K partials + bias ---
    float e[3], v[3];
    if (tid < 256) {
        #pragma unroll
        for (int h = 0; h < 3; h++) {
            int o = b * NL + h * 256 + tid;
            v[h] = g_attP[o] + g_attP[Bb*NL + o] + g_attP[2*Bb*NL + o] + g_attP[3*Bb*NL + o]
                 + g_biasA[h * 256 + tid];
        }
        int w8 = tid >> 5;
        #pragma unroll
        for (int h = 0; h < 3; h++) {
            float m = v[h];
            #pragma unroll
            for (int o = 16; o; o >>= 1) m = fmaxf(m, __shfl_xor_sync(0xffffffffu, m, o));
            if ((tid & 31) == 0) red[h][w8] = m;
        }
    }
    __syncthreads();
    if (tid < 256) {
        int w8 = tid >> 5;
        #pragma unroll
        for (int h = 0; h < 3; h++) {
            float mm = red[h][0];
            #pragma unroll
            for (int q = 1; q < 8; q++) mm = fmaxf(mm, red[h][q]);
            e[h] = expf(v[h] - mm);
        }
        __syncthreads();
        #pragma unroll
        for (int h = 0; h < 3; h++) {
            float s = e[h];
            #pragma unroll
            for (int o = 16; o; o >>= 1) s += __shfl_xor_sync(0xffffffffu, s, o);
            if ((tid & 31) == 0) red[h][w8] = s;
        }
    } else {
        __syncthreads();
    }
    __syncthreads();
    if (tid < 256) {
        #pragma unroll
        for (int h = 0; h < 3; h++) {
            float s = red[h][0];
            #pragma unroll
            for (int q = 1; q < 8; q++) s += red[h][q];
            a[h][tid] = e[h] / s;
        }
    }
    __syncthreads();

    // --- value gather over this CTA's D-half: 192 half2 cols, L split 2-way ---
    const int ty = tid / 192, tx = tid % 192;     // ty 0..1
    const __half2* xb2 = (const __half2*)g_xh + (size_t)b * Ll * (Dd/2) + half * 192;
    float2 s0 = {0,0}, s1 = {0,0}, s2 = {0,0};
    const int l0 = ty * 128;
    #pragma unroll 8
    for (int l = l0; l < l0 + 128; l++) {
        float w0 = a[0][l], w1 = a[1][l], w2 = a[2][l];
        float2 xv = __half22float2(xb2[(size_t)l * 384 + tx]);
        s0.x += w0*xv.x; s0.y += w0*xv.y;
        s1.x += w1*xv.x; s1.y += w1*xv.y;
        s2.x += w2*xv.x; s2.y += w2*xv.y;
    }
    part[0][ty][tx] = s0; part[1][ty][tx] = s1; part[2][ty][tx] = s2;
    __syncthreads();

    // reduce + fp16 write: 3 heads x 192 half2 = 576 items over 384 threads
    __half2* vout = (__half2*)(g_A + (size_t)par * BKA);
    for (int sIdx = tid; sIdx < 576; sIdx += 384) {
        int h = sIdx / 192, c = sIdx % 192;
        float2 r0 = part[h][0][c], r1 = part[h][1][c];
        size_t o = ((size_t)b * KA + h * Dd + half * 384) / 2 + c;
        vout[o] = __floats2half2_rn(r0.x + r1.x, r0.y + r1.y);
    }
}

// ======================= driver (single stream, graph-safe) =======================
extern "C" void kernel_launch(void* const* d_in, const int* in_sizes, int n_in,
                              void* d_out, int out_size) {
    (void)in_sizes; (void)n_in; (void)out_size;
    const float* x    = (const float*)d_in[0];
    const float* h0   = (const float*)d_in[1];
    const float* c0   = (const float*)d_in[2];
    const float* W1   = (const float*)d_in[3];
    const float* b1   = (const float*)d_in[4];
    const float* W2   = (const float*)d_in[5];
    const float* b2   = (const float*)d_in[6];
    const float* W3   = (const float*)d_in[7];
    const float* b3   = (const float*)d_in[8];
    const float* W_ih = (const float*)d_in[9];
    const float* W_hh = (const float*)d_in[10];
    const float* b_ih = (const float*)d_in[11];
    const float* b_hh = (const float*)d_in[12];
    float* out = (float*)d_out;

    cudaFuncSetAttribute(logits_kernel, cudaFuncAttributeMaxDynamicSharedMemorySize, SMEM2);
    cudaFuncSetAttribute(gates_kernel,  cudaFuncAttributeMaxDynamicSharedMemorySize, SMEM2);

    __half *wah, *wal;
    cudaGetSymbolAddress((void**)&wah, g_Wah);
    cudaGetSymbolAddress((void**)&wal, g_Wal);

    x2h_kernel<<<2048, 256>>>(x);
    reorder_ih_kernel<<<4096, 256>>>(W_ih);
    reorder_hh_kernel<<<4096, 256>>>(W_hh);
    split_h_kernel<<<1024, 256>>>(W1, wah,           wal,           Ll*Hh);
    split_h_kernel<<<1024, 256>>>(W2, wah + Ll*Hh,   wal + Ll*Hh,   Ll*Hh);
    split_h_kernel<<<1024, 256>>>(W3, wah + 2*Ll*Hh, wal + 2*Ll*Hh, Ll*Hh);
    bias_prep_kernel<<<16, 256>>>(b_ih, b_hh, b1, b2, b3);
    init_kernel<<<(BH + 255)/256, 256>>>(h0, c0);

    for (int t = 0; t < Tt; t++) {
        const int par = t & 1;
        logits_kernel<<<96, 128, SMEM2>>>(par);            // split-K-4 logits partials
        attnv_kernel<<<512, 384>>>(par);                   // softmax + fp16 value gather
        gates_kernel<<<256, 128, SMEM2>>>(par);            // [v|h] GEMM, split-K-2, one wave
        lstm_kernel<<<BH/256, 256>>>(out, t);              // combine partials + LSTM
    }
}

// round 15
// speedup vs baseline: 1.6505x; 1.2169x over previous
#include <cuda_runtime.h>
#include <cuda_bf16.h>
#include <cuda_fp16.h>
#include <mma.h>
#include <cstdint>
#include <math.h>

using namespace nvcuda;

#define Bb 256
#define Ll 256
#define Dd 768
#define Hh 1024
#define Tt 32
#define KV (3*Dd)      // 2304
#define KA2 (KV+2*Hh)  // 4352: [v | h | h]
#define Gg (4*Hh)      // 4096
#define NL (3*Ll)      // 768
#define KCH 64
#define LDS 72         // padded smem stride (elems), 144 B
#define BH (Bb*Hh)
#define BKA2 ((size_t)Bb*KA2)

// 1-term GEMM tile: 64x128 CTA, 128 threads (4 warps 2x2), warp tile 32x64
#define BMg 64
#define BNg 128
#define SS1 ((BMg + BNg) * LDS * 2)         // 27648 B per stage
#define BOFF1 (BMg * LDS * 2)                // 9216
#define SMEM1 (2 * SS1)                      // 55296

// ======================= device scratch =======================
__device__ float g_c[BH];
__device__ float g_attP[4*Bb*NL];                  // logits split-K-4 partials
__device__ float g_ih0[Bb*Gg], g_ih1[Bb*Gg];       // gates split-K partials (gate-interleaved)
__device__ float g_biasG[Gg];             // reordered: [unit*4+gate]
__device__ float g_biasA[NL];
__device__ __align__(16) __half g_xh[Bb*Ll*Dd];    // x in fp16
// A = [v | h | h], fp16, double-buffered by step parity
__device__ __align__(16) __half g_A[2*Bb*KA2];
__device__ __align__(16) __half g_WA[NL*Hh];                   // logits weights, single fp16
__device__ __align__(16) __half g_WG[(size_t)Gg*KA2];          // [Wih | Whh_hi | Whh_lo], gate-interleaved rows

__device__ __forceinline__ void split2h(float a, __half* hi, __half* lo) {
    __half h = __float2half_rn(a);
    *hi = h;
    *lo = __float2half_rn(a - __half2float(h));
}
__device__ __forceinline__ uint32_t smem_u32(const void* p) {
    uint32_t a;
    asm("{ .reg .u64 t; cvta.to.shared.u64 t, %1; cvt.u32.u64 %0, t; }" : "=r"(a) : "l"(p));
    return a;
}
__device__ __forceinline__ void cp16(uint32_t s, const void* g) {
    asm volatile("cp.async.cg.shared.global [%0], [%1], 16;" :: "r"(s), "l"(g));
}
#define CP_COMMIT() asm volatile("cp.async.commit_group;" ::: "memory")
#define CP_WAIT(n)  asm volatile("cp.async.wait_group %0;" :: "n"(n) : "memory")
__device__ __forceinline__ float sigmoidf_(float x) { return 1.0f / (1.0f + expf(-x)); }

// ======================= prep kernels =======================
__global__ void x2h_kernel(const float* __restrict__ x) {
    __half2* dst = (__half2*)g_xh;
    const float2* src = (const float2*)x;
    int n2 = Bb*Ll*Dd/2;
    for (int i = blockIdx.x * blockDim.x + threadIdx.x; i < n2; i += gridDim.x * blockDim.x) {
        float2 f = src[i];
        dst[i] = __floats2half2_rn(f.x, f.y);
    }
}

// W1/W2/W3 -> g_WA single fp16 (concat rows)
__global__ void wa_kernel(const float* __restrict__ src, int rowOff, int n) {
    for (int i = blockIdx.x * blockDim.x + threadIdx.x; i < n; i += gridDim.x * blockDim.x)
        g_WA[(size_t)rowOff * Hh + i] = __float2half_rn(src[i]);
}

// W_ih [4096 x 2304]: row gate*1024+unit -> row' unit*4+gate, single fp16, cols [0,2304)
__global__ void reorder_ih_kernel(const float* __restrict__ src) {
    for (int i = blockIdx.x * blockDim.x + threadIdx.x; i < Gg*KV; i += gridDim.x * blockDim.x) {
        int r = i / KV, k = i - r * KV;
        int gate = r >> 10, unit = r & 1023;
        g_WG[(size_t)(unit * 4 + gate) * KA2 + k] = __float2half_rn(src[i]);
    }
}
// W_hh [4096 x 1024]: hi at cols [2304,3328), lo at [3328,4352)
__global__ void reorder_hh_kernel(const float* __restrict__ src) {
    for (int i = blockIdx.x * blockDim.x + threadIdx.x; i < Gg*Hh; i += gridDim.x * blockDim.x) {
        int r = i / Hh, k = i - r * Hh;
        int gate = r >> 10, unit = r & 1023;
        size_t base = (size_t)(unit * 4 + gate) * KA2;
        split2h(src[i], &g_WG[base + KV + k], &g_WG[base + KV + Hh + k]);
    }
}

__global__ void bias_prep_kernel(const float* __restrict__ b_ih, const float* __restrict__ b_hh,
                                 const float* __restrict__ b1, const float* __restrict__ b2,
                                 const float* __restrict__ b3) {
    int j = blockIdx.x * blockDim.x + threadIdx.x;
    if (j < Gg) {
        int gate = j >> 10, unit = j & 1023;
        g_biasG[unit * 4 + gate] = b_ih[j] + b_hh[j];
    }
    if (j < NL) g_biasA[j] = (j < Ll) ? b1[j] : (j < 2*Ll) ? b2[j - Ll] : b3[j - 2*Ll];
}

__global__ void init_kernel(const float* __restrict__ h0, const float* __restrict__ c0) {
    int i = blockIdx.x * blockDim.x + threadIdx.x;
    if (i < BH) {
        int row = i >> 10, u = i & 1023;
        __half hv = __float2half_rn(h0[i]);
        g_A[(size_t)row * KA2 + KV + u] = hv;        // h slot 1 (Whh_hi)
        g_A[(size_t)row * KA2 + KV + Hh + u] = hv;   // h slot 2 (Whh_lo)
        g_c[i] = c0[i];
    }
}

// ======================= 1-term fp16 GEMM core (64x128 tile, 128 thr, warps 2x2) ========
template <int NCH>
__device__ __forceinline__ void gemm_core1(
    char* smem, uint32_t sb, int tid,
    const __half* __restrict__ A, const __half* __restrict__ W,
    int lda, int ldb, int row0, int col0,
    wmma::fragment<wmma::accumulator, 16, 16, 16, float> (&acc)[2][4],
    int wm, int wn)
{
    auto load_chunk = [&](int kc, int s) {
        const int ka = kc * KCH;
        const uint32_t st = sb + s * SS1;
        #pragma unroll
        for (int it = 0; it < 4; it++) {                 // A: 64 rows
            int idx = tid + it * 128, r = idx >> 3, q = idx & 7;
            size_t src = (size_t)(row0 + r) * lda + ka + q * 8;
            uint32_t off = r * (LDS*2) + q * 16;
            cp16(st + off, A + src);
        }
        #pragma unroll
        for (int it = 0; it < 8; it++) {                 // W: 128 rows
            int idx = tid + it * 128, r = idx >> 3, q = idx & 7;
            size_t src = (size_t)(col0 + r) * ldb + ka + q * 8;
            uint32_t off = r * (LDS*2) + q * 16;
            cp16(st + BOFF1 + off, W + src);
        }
    };

    load_chunk(0, 0); CP_COMMIT();
    for (int kc = 0; kc < NCH; kc++) {
        if (kc + 1 < NCH) { load_chunk(kc + 1, (kc + 1) & 1); CP_COMMIT(); CP_WAIT(1); }
        else              { CP_WAIT(0); }
        __syncthreads();
        const char* st = smem + (kc & 1) * SS1;
        const __half* pA = (const __half*)st;
        const __half* pB = (const __half*)(st + BOFF1);
        #pragma unroll
        for (int k16 = 0; k16 < KCH/16; k16++) {
            const int kk = k16 * 16;
            wmma::fragment<wmma::matrix_a, 16, 16, 16, __half, wmma::row_major> af[2];
            #pragma unroll
            for (int i = 0; i < 2; i++)
                wmma::load_matrix_sync(af[i], pA + (wm * 32 + i * 16) * LDS + kk, LDS);
            #pragma unroll
            for (int j = 0; j < 4; j++) {
                wmma::fragment<wmma::matrix_b, 16, 16, 16, __half, wmma::col_major> bw;
                wmma::load_matrix_sync(bw, pB + (wn * 64 + j * 16) * LDS + kk, LDS);
                #pragma unroll
                for (int i = 0; i < 2; i++)
                    wmma::mma_sync(acc[i][j], af[i], bw, acc[i][j]);
            }
        }
        __syncthreads();
    }
}

// ======================= logits, split-K 4-way, 1-term fp16 =======================
// 96 CTAs x 128 thr: quarter = bid/24, tile = bid%24 (4m x 6n). K=256 per quarter.
__global__ void __launch_bounds__(128) logits_kernel(int par) {
    extern __shared__ __align__(16) char smem[];
    const uint32_t sb = smem_u32(smem);
    const int tid = threadIdx.x, wid = tid >> 5, wm = wid >> 1, wn = wid & 1;
    const int bid = blockIdx.x;
    const int quar = bid / 24, tt = bid % 24;
    const int m_t = tt & 3, n_t = tt >> 2;      // n_t 0..5
    const int row0 = m_t * BMg, col0 = n_t * BNg;
    const int ko = quar * 256;
    float* C = g_attP + quar * (Bb * NL);
    const __half* A = g_A + (size_t)par * BKA2 + KV;  // h slot 1, row stride KA2

    wmma::fragment<wmma::accumulator, 16, 16, 16, float> acc[2][4];
    #pragma unroll
    for (int i = 0; i < 2; i++) for (int j = 0; j < 4; j++) wmma::fill_fragment(acc[i][j], 0.0f);

    gemm_core1<4>(smem, sb, tid, A + ko, g_WA + ko, KA2, Hh, row0, col0, acc, wm, wn);

    #pragma unroll
    for (int i = 0; i < 2; i++)
        #pragma unroll
        for (int j = 0; j < 4; j++) {
            int row = row0 + wm * 32 + i * 16;
            int col = col0 + wn * 64 + j * 16;
            wmma::store_matrix_sync(&C[(size_t)row * NL + col], acc[i][j], NL, wmma::mem_row_major);
        }
}

// ======================= gates GEMM: [v|h|h] @ [Wih|Whh_hi|Whh_lo]^T, split-K 2-way =====
// 256 CTAs x 128 thr: half = bid>>7, tile (4m x 32n). K=4352 -> 34 chunks per half.
__global__ void __launch_bounds__(128) gates_kernel(int par) {
    extern __shared__ __align__(16) char smem[];
    const uint32_t sb = smem_u32(smem);
    const int tid = threadIdx.x, wid = tid >> 5, wm = wid >> 1, wn = wid & 1;
    const int bid = blockIdx.x;
    const int half = bid >> 7, tt = bid & 127;
    const int m_t = tt & 3, n_t = tt >> 2;      // n_t 0..31
    const int row0 = m_t * BMg, col0 = n_t * BNg;
    const int ko = half * 2176;                 // 34 * 64
    float* C = half ? g_ih1 : g_ih0;
    const __half* A = g_A + (size_t)par * BKA2;

    wmma::fragment<wmma::accumulator, 16, 16, 16, float> acc[2][4];
    #pragma unroll
    for (int i = 0; i < 2; i++) for (int j = 0; j < 4; j++) wmma::fill_fragment(acc[i][j], 0.0f);

    gemm_core1<34>(smem, sb, tid, A + ko, g_WG + ko, KA2, KA2, row0, col0, acc, wm, wn);

    #pragma unroll
    for (int i = 0; i < 2; i++)
        #pragma unroll
        for (int j = 0; j < 4; j++) {
            int row = row0 + wm * 32 + i * 16;
            int col = col0 + wn * 64 + j * 16;
            wmma::store_matrix_sync(&C[(size_t)row * Gg + col], acc[i][j], Gg, wmma::mem_row_major);
        }
}

// ======================= LSTM pointwise: sum 2 partials + bias =======================
__global__ void __launch_bounds__(256) lstm_kernel(float* __restrict__ out, int t_step) {
    int idx = blockIdx.x * blockDim.x + threadIdx.x;  // B*H
    int row = idx >> 10, u = idx & 1023;
    const int par = t_step & 1;
    size_t go = (size_t)row * Gg + u * 4;
    float4 a0 = *(const float4*)&g_ih0[go];
    float4 a1 = *(const float4*)&g_ih1[go];
    float4 bv = *(const float4*)&g_biasG[u * 4];
    float ig = a0.x + a1.x + bv.x;
    float fg = a0.y + a1.y + bv.y;
    float gg = a0.z + a1.z + bv.z;
    float og = a0.w + a1.w + bv.w;
    float c = g_c[idx];
    float cn = sigmoidf_(fg) * c + sigmoidf_(ig) * tanhf(gg);
    float hn = sigmoidf_(og) * tanhf(cn);
    g_c[idx] = cn;
    __half hv = __float2half_rn(hn);
    size_t ab = (size_t)(par ^ 1) * BKA2 + (size_t)row * KA2;
    g_A[ab + KV + u] = hv;            // h slot 1
    g_A[ab + KV + Hh + u] = hv;       // h slot 2
    out[((size_t)row * Tt + t_step) * Hh + u] = hn;
}

// ======================= fused softmax + attention-value (fp16 x), D-split 2-way ========
// 512 CTAs x 384 thr: bid = b*2 + half. Writes v (fp16) into g_A[par] v-part.
__global__ void __launch_bounds__(384, 4) attnv_kernel(int par) {
    const int bid = blockIdx.x;
    const int b = bid >> 1, half = bid & 1;
    const int tid = threadIdx.x;

    __shared__ float a[3][Ll];
    __shared__ float2 part[3][2][192];
    __shared__ float red[3][8];

    // --- softmax (threads 0..255), logits = sum of 4 split-K partials + bias ---
    float e[3], v[3];
    if (tid < 256) {
        #pragma unroll
        for (int h = 0; h < 3; h++) {
            int o = b * NL + h * 256 + tid;
            v[h] = g_attP[o] + g_attP[Bb*NL + o] + g_attP[2*Bb*NL + o] + g_attP[3*Bb*NL + o]
                 + g_biasA[h * 256 + tid];
        }
        int w8 = tid >> 5;
        #pragma unroll
        for (int h = 0; h < 3; h++) {
            float m = v[h];
            #pragma unroll
            for (int o = 16; o; o >>= 1) m = fmaxf(m, __shfl_xor_sync(0xffffffffu, m, o));
            if ((tid & 31) == 0) red[h][w8] = m;
        }
    }
    __syncthreads();
    if (tid < 256) {
        int w8 = tid >> 5;
        #pragma unroll
        for (int h = 0; h < 3; h++) {
            float mm = red[h][0];
            #pragma unroll
            for (int q = 1; q < 8; q++) mm = fmaxf(mm, red[h][q]);
            e[h] = expf(v[h] - mm);
        }
        __syncthreads();
        #pragma unroll
        for (int h = 0; h < 3; h++) {
            float s = e[h];
            #pragma unroll
            for (int o = 16; o; o >>= 1) s += __shfl_xor_sync(0xffffffffu, s, o);
            if ((tid & 31) == 0) red[h][w8] = s;
        }
    } else {
        __syncthreads();
    }
    __syncthreads();
    if (tid < 256) {
        #pragma unroll
        for (int h = 0; h < 3; h++) {
            float s = red[h][0];
            #pragma unroll
            for (int q = 1; q < 8; q++) s += red[h][q];
            a[h][tid] = e[h] / s;
        }
    }
    __syncthreads();

    // --- value gather over this CTA's D-half: 192 half2 cols, L split 2-way ---
    const int ty = tid / 192, tx = tid % 192;     // ty 0..1
    const __half2* xb2 = (const __half2*)g_xh + (size_t)b * Ll * (Dd/2) + half * 192;
    float2 s0 = {0,0}, s1 = {0,0}, s2 = {0,0};
    const int l0 = ty * 128;
    #pragma unroll 8
    for (int l = l0; l < l0 + 128; l++) {
        float w0 = a[0][l], w1 = a[1][l], w2 = a[2][l];
        float2 xv = __half22float2(xb2[(size_t)l * 384 + tx]);
        s0.x += w0*xv.x; s0.y += w0*xv.y;
        s1.x += w1*xv.x; s1.y += w1*xv.y;
        s2.x += w2*xv.x; s2.y += w2*xv.y;
    }
    part[0][ty][tx] = s0; part[1][ty][tx] = s1; part[2][ty][tx] = s2;
    __syncthreads();

    // reduce + fp16 write: 3 heads x 192 half2 = 576 items over 384 threads
    __half2* vout = (__half2*)(g_A + (size_t)par * BKA2);
    for (int sIdx = tid; sIdx < 576; sIdx += 384) {
        int h = sIdx / 192, c = sIdx % 192;
        float2 r0 = part[h][0][c], r1 = part[h][1][c];
        size_t o = ((size_t)b * KA2 + h * Dd + half * 384) / 2 + c;
        vout[o] = __floats2half2_rn(r0.x + r1.x, r0.y + r1.y);
    }
}

// ======================= driver (single stream, graph-safe) =======================
extern "C" void kernel_launch(void* const* d_in, const int* in_sizes, int n_in,
                              void* d_out, int out_size) {
    (void)in_sizes; (void)n_in; (void)out_size;
    const float* x    = (const float*)d_in[0];
    const float* h0   = (const float*)d_in[1];
    const float* c0   = (const float*)d_in[2];
    const float* W1   = (const float*)d_in[3];
    const float* b1   = (const float*)d_in[4];
    const float* W2   = (const float*)d_in[5];
    const float* b2   = (const float*)d_in[6];
    const float* W3   = (const float*)d_in[7];
    const float* b3   = (const float*)d_in[8];
    const float* W_ih = (const float*)d_in[9];
    const float* W_hh = (const float*)d_in[10];
    const float* b_ih = (const float*)d_in[11];
    const float* b_hh = (const float*)d_in[12];
    float* out = (float*)d_out;

    cudaFuncSetAttribute(logits_kernel, cudaFuncAttributeMaxDynamicSharedMemorySize, SMEM1);
    cudaFuncSetAttribute(gates_kernel,  cudaFuncAttributeMaxDynamicSharedMemorySize, SMEM1);

    x2h_kernel<<<2048, 256>>>(x);
    reorder_ih_kernel<<<4096, 256>>>(W_ih);
    reorder_hh_kernel<<<4096, 256>>>(W_hh);
    wa_kernel<<<1024, 256>>>(W1, 0,      Ll*Hh);
    wa_kernel<<<1024, 256>>>(W2, Ll,     Ll*Hh);
    wa_kernel<<<1024, 256>>>(W3, 2*Ll,   Ll*Hh);
    bias_prep_kernel<<<16, 256>>>(b_ih, b_hh, b1, b2, b3);
    init_kernel<<<(BH + 255)/256, 256>>>(h0, c0);

    for (int t = 0; t < Tt; t++) {
        const int par = t & 1;
        logits_kernel<<<96, 128, SMEM1>>>(par);            // split-K-4 logits, 1-term
        attnv_kernel<<<512, 384>>>(par);                   // softmax + fp16 value gather
        gates_kernel<<<256, 128, SMEM1>>>(par);            // [v|h|h] GEMM, split-K-2
        lstm_kernel<<<BH/256, 256>>>(out, t);              // combine partials + LSTM
    }
}

// round 16
// speedup vs baseline: 1.7083x; 1.0351x over previous
#include <cuda_runtime.h>
#include <cuda_bf16.h>
#include <cuda_fp16.h>
#include <mma.h>
#include <cstdint>
#include <math.h>

using namespace nvcuda;

#define Bb 256
#define Ll 256
#define Dd 768
#define Hh 1024
#define Tt 32
#define KV (3*Dd)      // 2304
#define KA2 (KV+2*Hh)  // 4352: [v | h | h]
#define Gg (4*Hh)      // 4096
#define NL (3*Ll)      // 768
#define KCH 64
#define LDS 72         // padded smem stride (elems), 144 B
#define BH (Bb*Hh)
#define BKA2 ((size_t)Bb*KA2)

// 1-term GEMM tile: 64x128 CTA, 128 threads (4 warps 2x2), warp tile 32x64
#define BMg 64
#define BNg 128
#define SS1 ((BMg + BNg) * LDS * 2)         // 27648 B per stage
#define BOFF1 (BMg * LDS * 2)                // 9216
#define SMEM1 (2 * SS1)                      // 55296

// ======================= device scratch =======================
__device__ float g_c[BH];
__device__ float g_attP[4*Bb*NL];                  // logits split-K-4 partials
__device__ float g_ih0[Bb*Gg], g_ih1[Bb*Gg];       // gates split-K partials (gate-interleaved)
__device__ float g_biasG[Gg];             // reordered: [unit*4+gate]
__device__ float g_biasA[NL];
__device__ __align__(16) __half g_xh[Bb*Ll*Dd];    // x in fp16
// A = [v | h | h], fp16, double-buffered by step parity
__device__ __align__(16) __half g_A[2*Bb*KA2];
__device__ __align__(16) __half g_WA[NL*Hh];                   // logits weights, single fp16
__device__ __align__(16) __half g_WG[(size_t)Gg*KA2];          // [Wih | Whh_hi | Whh_lo], gate-interleaved rows

__device__ __forceinline__ void split2h(float a, __half* hi, __half* lo) {
    __half h = __float2half_rn(a);
    *hi = h;
    *lo = __float2half_rn(a - __half2float(h));
}
__device__ __forceinline__ uint32_t smem_u32(const void* p) {
    uint32_t a;
    asm("{ .reg .u64 t; cvta.to.shared.u64 t, %1; cvt.u32.u64 %0, t; }" : "=r"(a) : "l"(p));
    return a;
}
__device__ __forceinline__ void cp16(uint32_t s, const void* g) {
    asm volatile("cp.async.cg.shared.global [%0], [%1], 16;" :: "r"(s), "l"(g));
}
#define CP_COMMIT() asm volatile("cp.async.commit_group;" ::: "memory")
#define CP_WAIT(n)  asm volatile("cp.async.wait_group %0;" :: "n"(n) : "memory")

// fast transcendentals (|rel err| ~1e-6, invisible under fp16-path noise)
__device__ __forceinline__ float fsig(float x) {
    return __fdividef(1.0f, 1.0f + __expf(-x));
}
__device__ __forceinline__ float ftanh_(float x) {
    float xc = fminf(fmaxf(x, -15.0f), 15.0f);
    float e = __expf(2.0f * xc);
    return __fdividef(e - 1.0f, e + 1.0f);
}

// ======================= prep kernels =======================
__global__ void x2h_kernel(const float* __restrict__ x) {
    __half2* dst = (__half2*)g_xh;
    const float2* src = (const float2*)x;
    int n2 = Bb*Ll*Dd/2;
    for (int i = blockIdx.x * blockDim.x + threadIdx.x; i < n2; i += gridDim.x * blockDim.x) {
        float2 f = src[i];
        dst[i] = __floats2half2_rn(f.x, f.y);
    }
}

// W1/W2/W3 -> g_WA single fp16 (concat rows)
__global__ void wa_kernel(const float* __restrict__ src, int rowOff, int n) {
    for (int i = blockIdx.x * blockDim.x + threadIdx.x; i < n; i += gridDim.x * blockDim.x)
        g_WA[(size_t)rowOff * Hh + i] = __float2half_rn(src[i]);
}

// W_ih [4096 x 2304]: row gate*1024+unit -> row' unit*4+gate, single fp16, cols [0,2304)
__global__ void reorder_ih_kernel(const float* __restrict__ src) {
    for (int i = blockIdx.x * blockDim.x + threadIdx.x; i < Gg*KV; i += gridDim.x * blockDim.x) {
        int r = i / KV, k = i - r * KV;
        int gate = r >> 10, unit = r & 1023;
        g_WG[(size_t)(unit * 4 + gate) * KA2 + k] = __float2half_rn(src[i]);
    }
}
// W_hh [4096 x 1024]: hi at cols [2304,3328), lo at [3328,4352)
__global__ void reorder_hh_kernel(const float* __restrict__ src) {
    for (int i = blockIdx.x * blockDim.x + threadIdx.x; i < Gg*Hh; i += gridDim.x * blockDim.x) {
        int r = i / Hh, k = i - r * Hh;
        int gate = r >> 10, unit = r & 1023;
        size_t base = (size_t)(unit * 4 + gate) * KA2;
        split2h(src[i], &g_WG[base + KV + k], &g_WG[base + KV + Hh + k]);
    }
}

__global__ void bias_prep_kernel(const float* __restrict__ b_ih, const float* __restrict__ b_hh,
                                 const float* __restrict__ b1, const float* __restrict__ b2,
                                 const float* __restrict__ b3) {
    int j = blockIdx.x * blockDim.x + threadIdx.x;
    if (j < Gg) {
        int gate = j >> 10, unit = j & 1023;
        g_biasG[unit * 4 + gate] = b_ih[j] + b_hh[j];
    }
    if (j < NL) g_biasA[j] = (j < Ll) ? b1[j] : (j < 2*Ll) ? b2[j - Ll] : b3[j - 2*Ll];
}

__global__ void init_kernel(const float* __restrict__ h0, const float* __restrict__ c0) {
    int i = blockIdx.x * blockDim.x + threadIdx.x;
    if (i < BH) {
        int row = i >> 10, u = i & 1023;
        __half hv = __float2half_rn(h0[i]);
        g_A[(size_t)row * KA2 + KV + u] = hv;        // h slot 1 (Whh_hi)
        g_A[(size_t)row * KA2 + KV + Hh + u] = hv;   // h slot 2 (Whh_lo)
        g_c[i] = c0[i];
    }
}

// ======================= 1-term fp16 GEMM core (64x128 tile, 128 thr, warps 2x2) ========
template <int NCH>
__device__ __forceinline__ void gemm_core1(
    char* smem, uint32_t sb, int tid,
    const __half* __restrict__ A, const __half* __restrict__ W,
    int lda, int ldb, int row0, int col0,
    wmma::fragment<wmma::accumulator, 16, 16, 16, float> (&acc)[2][4],
    int wm, int wn)
{
    auto load_chunk = [&](int kc, int s) {
        const int ka = kc * KCH;
        const uint32_t st = sb + s * SS1;
        #pragma unroll
        for (int it = 0; it < 4; it++) {                 // A: 64 rows
            int idx = tid + it * 128, r = idx >> 3, q = idx & 7;
            size_t src = (size_t)(row0 + r) * lda + ka + q * 8;
            uint32_t off = r * (LDS*2) + q * 16;
            cp16(st + off, A + src);
        }
        #pragma unroll
        for (int it = 0; it < 8; it++) {                 // W: 128 rows
            int idx = tid + it * 128, r = idx >> 3, q = idx & 7;
            size_t src = (size_t)(col0 + r) * ldb + ka + q * 8;
            uint32_t off = r * (LDS*2) + q * 16;
            cp16(st + BOFF1 + off, W + src);
        }
    };

    load_chunk(0, 0); CP_COMMIT();
    for (int kc = 0; kc < NCH; kc++) {
        if (kc + 1 < NCH) { load_chunk(kc + 1, (kc + 1) & 1); CP_COMMIT(); CP_WAIT(1); }
        else              { CP_WAIT(0); }
        __syncthreads();
        const char* st = smem + (kc & 1) * SS1;
        const __half* pA = (const __half*)st;
        const __half* pB = (const __half*)(st + BOFF1);
        #pragma unroll
        for (int k16 = 0; k16 < KCH/16; k16++) {
            const int kk = k16 * 16;
            wmma::fragment<wmma::matrix_a, 16, 16, 16, __half, wmma::row_major> af[2];
            #pragma unroll
            for (int i = 0; i < 2; i++)
                wmma::load_matrix_sync(af[i], pA + (wm * 32 + i * 16) * LDS + kk, LDS);
            #pragma unroll
            for (int j = 0; j < 4; j++) {
                wmma::fragment<wmma::matrix_b, 16, 16, 16, __half, wmma::col_major> bw;
                wmma::load_matrix_sync(bw, pB + (wn * 64 + j * 16) * LDS + kk, LDS);
                #pragma unroll
                for (int i = 0; i < 2; i++)
                    wmma::mma_sync(acc[i][j], af[i], bw, acc[i][j]);
            }
        }
        __syncthreads();
    }
}

// ======================= logits, split-K 4-way, 1-term fp16 =======================
// 96 CTAs x 128 thr: quarter = bid/24, tile = bid%24 (4m x 6n). K=256 per quarter.
__global__ void __launch_bounds__(128) logits_kernel(int par) {
    extern __shared__ __align__(16) char smem[];
    const uint32_t sb = smem_u32(smem);
    const int tid = threadIdx.x, wid = tid >> 5, wm = wid >> 1, wn = wid & 1;
    const int bid = blockIdx.x;
    const int quar = bid / 24, tt = bid % 24;
    const int m_t = tt & 3, n_t = tt >> 2;      // n_t 0..5
    const int row0 = m_t * BMg, col0 = n_t * BNg;
    const int ko = quar * 256;
    float* C = g_attP + quar * (Bb * NL);
    const __half* A = g_A + (size_t)par * BKA2 + KV;  // h slot 1, row stride KA2

    wmma::fragment<wmma::accumulator, 16, 16, 16, float> acc[2][4];
    #pragma unroll
    for (int i = 0; i < 2; i++) for (int j = 0; j < 4; j++) wmma::fill_fragment(acc[i][j], 0.0f);

    gemm_core1<4>(smem, sb, tid, A + ko, g_WA + ko, KA2, Hh, row0, col0, acc, wm, wn);

    #pragma unroll
    for (int i = 0; i < 2; i++)
        #pragma unroll
        for (int j = 0; j < 4; j++) {
            int row = row0 + wm * 32 + i * 16;
            int col = col0 + wn * 64 + j * 16;
            wmma::store_matrix_sync(&C[(size_t)row * NL + col], acc[i][j], NL, wmma::mem_row_major);
        }
}

// ======================= gates GEMM: [v|h|h] @ [Wih|Whh_hi|Whh_lo]^T, split-K 2-way =====
// 256 CTAs x 128 thr: half = bid>>7, tile (4m x 32n). K=4352 -> 34 chunks per half.
__global__ void __launch_bounds__(128) gates_kernel(int par) {
    extern __shared__ __align__(16) char smem[];
    const uint32_t sb = smem_u32(smem);
    const int tid = threadIdx.x, wid = tid >> 5, wm = wid >> 1, wn = wid & 1;
    const int bid = blockIdx.x;
    const int half = bid >> 7, tt = bid & 127;
    const int m_t = tt & 3, n_t = tt >> 2;      // n_t 0..31
    const int row0 = m_t * BMg, col0 = n_t * BNg;
    const int ko = half * 2176;                 // 34 * 64
    float* C = half ? g_ih1 : g_ih0;
    const __half* A = g_A + (size_t)par * BKA2;

    wmma::fragment<wmma::accumulator, 16, 16, 16, float> acc[2][4];
    #pragma unroll
    for (int i = 0; i < 2; i++) for (int j = 0; j < 4; j++) wmma::fill_fragment(acc[i][j], 0.0f);

    gemm_core1<34>(smem, sb, tid, A + ko, g_WG + ko, KA2, KA2, row0, col0, acc, wm, wn);

    #pragma unroll
    for (int i = 0; i < 2; i++)
        #pragma unroll
        for (int j = 0; j < 4; j++) {
            int row = row0 + wm * 32 + i * 16;
            int col = col0 + wn * 64 + j * 16;
            wmma::store_matrix_sync(&C[(size_t)row * Gg + col], acc[i][j], Gg, wmma::mem_row_major);
        }
}

// ======================= LSTM pointwise: sum 2 partials + bias (fast math) =============
__global__ void __launch_bounds__(256) lstm_kernel(float* __restrict__ out, int t_step) {
    int idx = blockIdx.x * blockDim.x + threadIdx.x;  // B*H
    int row = idx >> 10, u = idx & 1023;
    const int par = t_step & 1;
    size_t go = (size_t)row * Gg + u * 4;
    float4 a0 = *(const float4*)&g_ih0[go];
    float4 a1 = *(const float4*)&g_ih1[go];
    float4 bv = *(const float4*)&g_biasG[u * 4];
    float ig = a0.x + a1.x + bv.x;
    float fg = a0.y + a1.y + bv.y;
    float gg = a0.z + a1.z + bv.z;
    float og = a0.w + a1.w + bv.w;
    float c = g_c[idx];
    float cn = fsig(fg) * c + fsig(ig) * ftanh_(gg);
    float hn = fsig(og) * ftanh_(cn);
    g_c[idx] = cn;
    __half hv = __float2half_rn(hn);
    size_t ab = (size_t)(par ^ 1) * BKA2 + (size_t)row * KA2;
    g_A[ab + KV + u] = hv;            // h slot 1
    g_A[ab + KV + Hh + u] = hv;       // h slot 2
    out[((size_t)row * Tt + t_step) * Hh + u] = hn;
}

// ======================= fused softmax + attention-value (fp16 x), D-split 2-way ========
// 512 CTAs x 384 thr: bid = b*2 + half. Value gather: L split 4-way, 8B loads.
__global__ void __launch_bounds__(384, 4) attnv_kernel(int par) {
    const int bid = blockIdx.x;
    const int b = bid >> 1, half = bid & 1;
    const int tid = threadIdx.x;

    __shared__ float a[3][Ll];
    __shared__ float4 part[3][4][96];
    __shared__ float red[3][8];

    // --- softmax (threads 0..255), logits = sum of 4 split-K partials + bias ---
    float e[3], v[3];
    if (tid < 256) {
        #pragma unroll
        for (int h = 0; h < 3; h++) {
            int o = b * NL + h * 256 + tid;
            v[h] = g_attP[o] + g_attP[Bb*NL + o] + g_attP[2*Bb*NL + o] + g_attP[3*Bb*NL + o]
                 + g_biasA[h * 256 + tid];
        }
        int w8 = tid >> 5;
        #pragma unroll
        for (int h = 0; h < 3; h++) {
            float m = v[h];
            #pragma unroll
            for (int o = 16; o; o >>= 1) m = fmaxf(m, __shfl_xor_sync(0xffffffffu, m, o));
            if ((tid & 31) == 0) red[h][w8] = m;
        }
    }
    __syncthreads();
    if (tid < 256) {
        int w8 = tid >> 5;
        #pragma unroll
        for (int h = 0; h < 3; h++) {
            float mm = red[h][0];
            #pragma unroll
            for (int q = 1; q < 8; q++) mm = fmaxf(mm, red[h][q]);
            e[h] = __expf(v[h] - mm);
        }
        __syncthreads();
        #pragma unroll
        for (int h = 0; h < 3; h++) {
            float s = e[h];
            #pragma unroll
            for (int o = 16; o; o >>= 1) s += __shfl_xor_sync(0xffffffffu, s, o);
            if ((tid & 31) == 0) red[h][w8] = s;
        }
    } else {
        __syncthreads();
    }
    __syncthreads();
    if (tid < 256) {
        #pragma unroll
        for (int h = 0; h < 3; h++) {
            float s = red[h][0];
            #pragma unroll
            for (int q = 1; q < 8; q++) s += red[h][q];
            a[h][tid] = __fdividef(e[h], s);
        }
    }
    __syncthreads();

    // --- value gather over this CTA's D-half: 96 uint2 cols (8B), L split 4-way ---
    const int ty = tid / 96, tx = tid % 96;       // ty 0..3
    const uint2* xb = (const uint2*)g_xh + (size_t)b * Ll * 192 + half * 96;
    float4 s0 = {0,0,0,0}, s1 = {0,0,0,0}, s2 = {0,0,0,0};
    const int l0 = ty * 64;
    #pragma unroll 8
    for (int l = l0; l < l0 + 64; l++) {
        float w0 = a[0][l], w1 = a[1][l], w2 = a[2][l];
        uint2 d = xb[(size_t)l * 192 + tx];
        float2 f0 = __half22float2(*(const __half2*)&d.x);
        float2 f1 = __half22float2(*(const __half2*)&d.y);
        s0.x += w0*f0.x; s0.y += w0*f0.y; s0.z += w0*f1.x; s0.w += w0*f1.y;
        s1.x += w1*f0.x; s1.y += w1*f0.y; s1.z += w1*f1.x; s1.w += w1*f1.y;
        s2.x += w2*f0.x; s2.y += w2*f0.y; s2.z += w2*f1.x; s2.w += w2*f1.y;
    }
    part[0][ty][tx] = s0; part[1][ty][tx] = s1; part[2][ty][tx] = s2;
    __syncthreads();

    // reduce + fp16 write: 3 heads x 96 uint2 (4 halves) = 288 items over 384 threads
    uint2* vout = (uint2*)(g_A + (size_t)par * BKA2);
    if (tid < 288) {
        int h = tid / 96, c = tid % 96;
        float4 r0 = part[h][0][c], r1 = part[h][1][c];
        float4 r2 = part[h][2][c], r3 = part[h][3][c];
        float rx = r0.x + r1.x + r2.x + r3.x;
        float ry = r0.y + r1.y + r2.y + r3.y;
        float rz = r0.z + r1.z + r2.z + r3.z;
        float rw = r0.w + r1.w + r2.w + r3.w;
        __half2 lo = __floats2half2_rn(rx, ry);
        __half2 hi = __floats2half2_rn(rz, rw);
        uint2 val;
        val.x = *(const uint32_t*)&lo;
        val.y = *(const uint32_t*)&hi;
        vout[((size_t)b * KA2 + h * Dd + half * 384) / 4 + c] = val;
    }
}

// ======================= driver (single stream, graph-safe) =======================
extern "C" void kernel_launch(void* const* d_in, const int* in_sizes, int n_in,
                              void* d_out, int out_size) {
    (void)in_sizes; (void)n_in; (void)out_size;
    const float* x    = (const float*)d_in[0];
    const float* h0   = (const float*)d_in[1];
    const float* c0   = (const float*)d_in[2];
    const float* W1   = (const float*)d_in[3];
    const float* b1   = (const float*)d_in[4];
    const float* W2   = (const float*)d_in[5];
    const float* b2   = (const float*)d_in[6];
    const float* W3   = (const float*)d_in[7];
    const float* b3   = (const float*)d_in[8];
    const float* W_ih = (const float*)d_in[9];
    const float* W_hh = (const float*)d_in[10];
    const float* b_ih = (const float*)d_in[11];
    const float* b_hh = (const float*)d_in[12];
    float* out = (float*)d_out;

    cudaFuncSetAttribute(logits_kernel, cudaFuncAttributeMaxDynamicSharedMemorySize, SMEM1);
    cudaFuncSetAttribute(gates_kernel,  cudaFuncAttributeMaxDynamicSharedMemorySize, SMEM1);

    x2h_kernel<<<2048, 256>>>(x);
    reorder_ih_kernel<<<4096, 256>>>(W_ih);
    reorder_hh_kernel<<<4096, 256>>>(W_hh);
    wa_kernel<<<1024, 256>>>(W1, 0,      Ll*Hh);
    wa_kernel<<<1024, 256>>>(W2, Ll,     Ll*Hh);
    wa_kernel<<<1024, 256>>>(W3, 2*Ll,   Ll*Hh);
    bias_prep_kernel<<<16, 256>>>(b_ih, b_hh, b1, b2, b3);
    init_kernel<<<(BH + 255)/256, 256>>>(h0, c0);

    for (int t = 0; t < Tt; t++) {
        const int par = t & 1;
        logits_kernel<<<96, 128, SMEM1>>>(par);            // split-K-4 logits, 1-term
        attnv_kernel<<<512, 384>>>(par);                   // softmax + fp16 value gather
        gates_kernel<<<256, 128, SMEM1>>>(par);            // [v|h|h] GEMM, split-K-2
        lstm_kernel<<<BH/256, 256>>>(out, t);              // combine partials + LSTM (fast math)
    }
}

// round 17
// speedup vs baseline: 1.7923x; 1.0491x over previous
#include <cuda_runtime.h>
#include <cuda_bf16.h>
#include <cuda_fp16.h>
#include <mma.h>
#include <cstdint>
#include <math.h>

using namespace nvcuda;

#define Bb 256
#define Ll 256
#define Dd 768
#define Hh 1024
#define Tt 32
#define KV (3*Dd)      // 2304
#define KA2 (KV+2*Hh)  // 4352: [v | h | h]
#define Gg (4*Hh)      // 4096
#define NL (3*Ll)      // 768
#define KCH 64
#define LDS 72         // padded smem stride (elems), 144 B
#define BH (Bb*Hh)
#define BKA2 ((size_t)Bb*KA2)

// 1-term GEMM tile: 64x128 CTA, 128 threads (4 warps 2x2), warp tile 32x64
#define BMg 64
#define BNg 128
#define SS1 ((BMg + BNg) * LDS * 2)         // 27648 B per stage
#define BOFF1 (BMg * LDS * 2)                // 9216
#define SMEM1 (2 * SS1)                      // 55296

// ======================= device scratch =======================
__device__ float g_c[BH];
__device__ float g_attP[4*Bb*NL];                  // logits split-K-4 partials
__device__ float g_ih0[Bb*Gg], g_ih1[Bb*Gg];       // gates split-K partials (gate-interleaved)
__device__ float g_biasG[Gg];             // reordered: [unit*4+gate]
__device__ float g_biasA[NL];
__device__ __align__(16) __half g_xh[Bb*Ll*Dd];    // x in fp16
// A = [v | h | h], fp16, double-buffered by step parity
__device__ __align__(16) __half g_A[2*Bb*KA2];
__device__ __align__(16) __half g_WA[NL*Hh];                   // logits weights, single fp16
__device__ __align__(16) __half g_WG[(size_t)Gg*KA2];          // [Wih | Whh_hi | Whh_lo], gate-interleaved rows

__device__ __forceinline__ void split2h(float a, __half* hi, __half* lo) {
    __half h = __float2half_rn(a);
    *hi = h;
    *lo = __float2half_rn(a - __half2float(h));
}
__device__ __forceinline__ uint32_t smem_u32(const void* p) {
    uint32_t a;
    asm("{ .reg .u64 t; cvta.to.shared.u64 t, %1; cvt.u32.u64 %0, t; }" : "=r"(a) : "l"(p));
    return a;
}
__device__ __forceinline__ void cp16(uint32_t s, const void* g) {
    asm volatile("cp.async.cg.shared.global [%0], [%1], 16;" :: "r"(s), "l"(g));
}
#define CP_COMMIT() asm volatile("cp.async.commit_group;" ::: "memory")
#define CP_WAIT(n)  asm volatile("cp.async.wait_group %0;" :: "n"(n) : "memory")

__device__ __forceinline__ float fsig(float x) {
    return __fdividef(1.0f, 1.0f + __expf(-x));
}
__device__ __forceinline__ float ftanh_(float x) {
    float xc = fminf(fmaxf(x, -15.0f), 15.0f);
    float e = __expf(2.0f * xc);
    return __fdividef(e - 1.0f, e + 1.0f);
}

// ======================= prep kernels (3 launches total) =======================
// prep 1: reorder + split W_ih (phase 0) and W_hh (phase 1) into g_WG
__global__ void prep_wg_kernel(const float* __restrict__ W_ih, const float* __restrict__ W_hh) {
    const int stride = gridDim.x * blockDim.x;
    for (int i = blockIdx.x * blockDim.x + threadIdx.x; i < Gg*KV; i += stride) {
        int r = i / KV, k = i - r * KV;
        int gate = r >> 10, unit = r & 1023;
        g_WG[(size_t)(unit * 4 + gate) * KA2 + k] = __float2half_rn(W_ih[i]);
    }
    for (int i = blockIdx.x * blockDim.x + threadIdx.x; i < Gg*Hh; i += stride) {
        int r = i / Hh, k = i - r * Hh;
        int gate = r >> 10, unit = r & 1023;
        size_t base = (size_t)(unit * 4 + gate) * KA2;
        split2h(W_hh[i], &g_WG[base + KV + k], &g_WG[base + KV + Hh + k]);
    }
}

// prep 2: x -> fp16, W1/W2/W3 -> g_WA
__global__ void prep_xwa_kernel(const float* __restrict__ x, const float* __restrict__ W1,
                                const float* __restrict__ W2, const float* __restrict__ W3) {
    const int stride = gridDim.x * blockDim.x;
    __half2* dst = (__half2*)g_xh;
    const float2* src = (const float2*)x;
    const int n2 = Bb*Ll*Dd/2;
    for (int i = blockIdx.x * blockDim.x + threadIdx.x; i < n2; i += stride) {
        float2 f = src[i];
        dst[i] = __floats2half2_rn(f.x, f.y);
    }
    const int nw = Ll*Hh;
    for (int i = blockIdx.x * blockDim.x + threadIdx.x; i < nw; i += stride) {
        g_WA[i] = __float2half_rn(W1[i]);
        g_WA[(size_t)Ll*Hh + i] = __float2half_rn(W2[i]);
        g_WA[(size_t)2*Ll*Hh + i] = __float2half_rn(W3[i]);
    }
}

// prep 3: biases + init h/c
__global__ void prep_init_kernel(const float* __restrict__ b_ih, const float* __restrict__ b_hh,
                                 const float* __restrict__ b1, const float* __restrict__ b2,
                                 const float* __restrict__ b3,
                                 const float* __restrict__ h0, const float* __restrict__ c0) {
    const int stride = gridDim.x * blockDim.x;
    for (int j = blockIdx.x * blockDim.x + threadIdx.x; j < Gg; j += stride) {
        int gate = j >> 10, unit = j & 1023;
        g_biasG[unit * 4 + gate] = b_ih[j] + b_hh[j];
    }
    for (int j = blockIdx.x * blockDim.x + threadIdx.x; j < NL; j += stride)
        g_biasA[j] = (j < Ll) ? b1[j] : (j < 2*Ll) ? b2[j - Ll] : b3[j - 2*Ll];
    for (int i = blockIdx.x * blockDim.x + threadIdx.x; i < BH; i += stride) {
        int row = i >> 10, u = i & 1023;
        __half hv = __float2half_rn(h0[i]);
        g_A[(size_t)row * KA2 + KV + u] = hv;
        g_A[(size_t)row * KA2 + KV + Hh + u] = hv;
        g_c[i] = c0[i];
    }
}

// ======================= 1-term fp16 GEMM core (64x128 tile, 128 thr, warps 2x2) ========
template <int NCH>
__device__ __forceinline__ void gemm_core1(
    char* smem, uint32_t sb, int tid,
    const __half* __restrict__ A, const __half* __restrict__ W,
    int lda, int ldb, int row0, int col0,
    wmma::fragment<wmma::accumulator, 16, 16, 16, float> (&acc)[2][4],
    int wm, int wn)
{
    auto load_chunk = [&](int kc, int s) {
        const int ka = kc * KCH;
        const uint32_t st = sb + s * SS1;
        #pragma unroll
        for (int it = 0; it < 4; it++) {                 // A: 64 rows
            int idx = tid + it * 128, r = idx >> 3, q = idx & 7;
            size_t src = (size_t)(row0 + r) * lda + ka + q * 8;
            uint32_t off = r * (LDS*2) + q * 16;
            cp16(st + off, A + src);
        }
        #pragma unroll
        for (int it = 0; it < 8; it++) {                 // W: 128 rows
            int idx = tid + it * 128, r = idx >> 3, q = idx & 7;
            size_t src = (size_t)(col0 + r) * ldb + ka + q * 8;
            uint32_t off = r * (LDS*2) + q * 16;
            cp16(st + BOFF1 + off, W + src);
        }
    };

    load_chunk(0, 0); CP_COMMIT();
    for (int kc = 0; kc < NCH; kc++) {
        if (kc + 1 < NCH) { load_chunk(kc + 1, (kc + 1) & 1); CP_COMMIT(); CP_WAIT(1); }
        else              { CP_WAIT(0); }
        __syncthreads();
        const char* st = smem + (kc & 1) * SS1;
        const __half* pA = (const __half*)st;
        const __half* pB = (const __half*)(st + BOFF1);
        #pragma unroll
        for (int k16 = 0; k16 < KCH/16; k16++) {
            const int kk = k16 * 16;
            wmma::fragment<wmma::matrix_a, 16, 16, 16, __half, wmma::row_major> af[2];
            #pragma unroll
            for (int i = 0; i < 2; i++)
                wmma::load_matrix_sync(af[i], pA + (wm * 32 + i * 16) * LDS + kk, LDS);
            #pragma unroll
            for (int j = 0; j < 4; j++) {
                wmma::fragment<wmma::matrix_b, 16, 16, 16, __half, wmma::col_major> bw;
                wmma::load_matrix_sync(bw, pB + (wn * 64 + j * 16) * LDS + kk, LDS);
                #pragma unroll
                for (int i = 0; i < 2; i++)
                    wmma::mma_sync(acc[i][j], af[i], bw, acc[i][j]);
            }
        }
        __syncthreads();
    }
}

// ======================= logits, split-K 4-way, 1-term fp16 =======================
__global__ void __launch_bounds__(128) logits_kernel(int par) {
    extern __shared__ __align__(16) char smem[];
    const uint32_t sb = smem_u32(smem);
    const int tid = threadIdx.x, wid = tid >> 5, wm = wid >> 1, wn = wid & 1;
    const int bid = blockIdx.x;
    const int quar = bid / 24, tt = bid % 24;
    const int m_t = tt & 3, n_t = tt >> 2;      // n_t 0..5
    const int row0 = m_t * BMg, col0 = n_t * BNg;
    const int ko = quar * 256;
    float* C = g_attP + quar * (Bb * NL);
    const __half* A = g_A + (size_t)par * BKA2 + KV;  // h slot 1, row stride KA2

    wmma::fragment<wmma::accumulator, 16, 16, 16, float> acc[2][4];
    #pragma unroll
    for (int i = 0; i < 2; i++) for (int j = 0; j < 4; j++) wmma::fill_fragment(acc[i][j], 0.0f);

    cudaGridDependencySynchronize();   // PDL: wait for lstm(t-1) writes before reading h

    gemm_core1<4>(smem, sb, tid, A + ko, g_WA + ko, KA2, Hh, row0, col0, acc, wm, wn);

    #pragma unroll
    for (int i = 0; i < 2; i++)
        #pragma unroll
        for (int j = 0; j < 4; j++) {
            int row = row0 + wm * 32 + i * 16;
            int col = col0 + wn * 64 + j * 16;
            wmma::store_matrix_sync(&C[(size_t)row * NL + col], acc[i][j], NL, wmma::mem_row_major);
        }
}

// ======================= gates GEMM: [v|h|h] @ [Wih|Whh_hi|Whh_lo]^T, split-K 2-way =====
__global__ void __launch_bounds__(128) gates_kernel(int par) {
    extern __shared__ __align__(16) char smem[];
    const uint32_t sb = smem_u32(smem);
    const int tid = threadIdx.x, wid = tid >> 5, wm = wid >> 1, wn = wid & 1;
    const int bid = blockIdx.x;
    const int half = bid >> 7, tt = bid & 127;
    const int m_t = tt & 3, n_t = tt >> 2;      // n_t 0..31
    const int row0 = m_t * BMg, col0 = n_t * BNg;
    const int ko = half * 2176;                 // 34 * 64
    float* C = half ? g_ih1 : g_ih0;
    const __half* A = g_A + (size_t)par * BKA2;

    wmma::fragment<wmma::accumulator, 16, 16, 16, float> acc[2][4];
    #pragma unroll
    for (int i = 0; i < 2; i++) for (int j = 0; j < 4; j++) wmma::fill_fragment(acc[i][j], 0.0f);

    cudaGridDependencySynchronize();   // PDL: wait for attnv's v writes

    gemm_core1<34>(smem, sb, tid, A + ko, g_WG + ko, KA2, KA2, row0, col0, acc, wm, wn);

    #pragma unroll
    for (int i = 0; i < 2; i++)
        #pragma unroll
        for (int j = 0; j < 4; j++) {
            int row = row0 + wm * 32 + i * 16;
            int col = col0 + wn * 64 + j * 16;
            wmma::store_matrix_sync(&C[(size_t)row * Gg + col], acc[i][j], Gg, wmma::mem_row_major);
        }
}

// ======================= LSTM pointwise: sum 2 partials + bias (fast math) =============
__global__ void __launch_bounds__(256) lstm_kernel(float* __restrict__ out, int t_step) {
    int idx = blockIdx.x * blockDim.x + threadIdx.x;  // B*H
    int row = idx >> 10, u = idx & 1023;
    const int par = t_step & 1;
    size_t go = (size_t)row * Gg + u * 4;

    cudaGridDependencySynchronize();   // PDL: wait for gates partials

    float4 a0 = *(const float4*)&g_ih0[go];
    float4 a1 = *(const float4*)&g_ih1[go];
    float4 bv = *(const float4*)&g_biasG[u * 4];
    float ig = a0.x + a1.x + bv.x;
    float fg = a0.y + a1.y + bv.y;
    float gg = a0.z + a1.z + bv.z;
    float og = a0.w + a1.w + bv.w;
    float c = g_c[idx];
    float cn = fsig(fg) * c + fsig(ig) * ftanh_(gg);
    float hn = fsig(og) * ftanh_(cn);
    g_c[idx] = cn;
    __half hv = __float2half_rn(hn);
    size_t ab = (size_t)(par ^ 1) * BKA2 + (size_t)row * KA2;
    g_A[ab + KV + u] = hv;            // h slot 1
    g_A[ab + KV + Hh + u] = hv;       // h slot 2
    out[((size_t)row * Tt + t_step) * Hh + u] = hn;
}

// ======================= fused softmax + attention-value (fp16 x), D-split 2-way ========
__global__ void __launch_bounds__(384, 4) attnv_kernel(int par) {
    const int bid = blockIdx.x;
    const int b = bid >> 1, half = bid & 1;
    const int tid = threadIdx.x;

    __shared__ float a[3][Ll];
    __shared__ float4 part[3][4][96];
    __shared__ float red[3][8];

    cudaGridDependencySynchronize();   // PDL: wait for logits partials

    // --- softmax (threads 0..255), logits = sum of 4 split-K partials + bias ---
    float e[3], v[3];
    if (tid < 256) {
        #pragma unroll
        for (int h = 0; h < 3; h++) {
            int o = b * NL + h * 256 + tid;
            v[h] = g_attP[o] + g_attP[Bb*NL + o] + g_attP[2*Bb*NL + o] + g_attP[3*Bb*NL + o]
                 + g_biasA[h * 256 + tid];
        }
        int w8 = tid >> 5;
        #pragma unroll
        for (int h = 0; h < 3; h++) {
            float m = v[h];
            #pragma unroll
            for (int o = 16; o; o >>= 1) m = fmaxf(m, __shfl_xor_sync(0xffffffffu, m, o));
            if ((tid & 31) == 0) red[h][w8] = m;
        }
    }
    __syncthreads();
    if (tid < 256) {
        int w8 = tid >> 5;
        #pragma unroll
        for (int h = 0; h < 3; h++) {
            float mm = red[h][0];
            #pragma unroll
            for (int q = 1; q < 8; q++) mm = fmaxf(mm, red[h][q]);
            e[h] = __expf(v[h] - mm);
        }
        __syncthreads();
        #pragma unroll
        for (int h = 0; h < 3; h++) {
            float s = e[h];
            #pragma unroll
            for (int o = 16; o; o >>= 1) s += __shfl_xor_sync(0xffffffffu, s, o);
            if ((tid & 31) == 0) red[h][w8] = s;
        }
    } else {
        __syncthreads();
    }
    __syncthreads();
    if (tid < 256) {
        #pragma unroll
        for (int h = 0; h < 3; h++) {
            float s = red[h][0];
            #pragma unroll
            for (int q = 1; q < 8; q++) s += red[h][q];
            a[h][tid] = __fdividef(e[h], s);
        }
    }
    __syncthreads();

    // --- value gather over this CTA's D-half: 96 uint2 cols (8B), L split 4-way ---
    const int ty = tid / 96, tx = tid % 96;       // ty 0..3
    const uint2* xb = (const uint2*)g_xh + (size_t)b * Ll * 192 + half * 96;
    float4 s0 = {0,0,0,0}, s1 = {0,0,0,0}, s2 = {0,0,0,0};
    const int l0 = ty * 64;
    #pragma unroll 8
    for (int l = l0; l < l0 + 64; l++) {
        float w0 = a[0][l], w1 = a[1][l], w2 = a[2][l];
        uint2 d = xb[(size_t)l * 192 + tx];
        float2 f0 = __half22float2(*(const __half2*)&d.x);
        float2 f1 = __half22float2(*(const __half2*)&d.y);
        s0.x += w0*f0.x; s0.y += w0*f0.y; s0.z += w0*f1.x; s0.w += w0*f1.y;
        s1.x += w1*f0.x; s1.y += w1*f0.y; s1.z += w1*f1.x; s1.w += w1*f1.y;
        s2.x += w2*f0.x; s2.y += w2*f0.y; s2.z += w2*f1.x; s2.w += w2*f1.y;
    }
    part[0][ty][tx] = s0; part[1][ty][tx] = s1; part[2][ty][tx] = s2;
    __syncthreads();

    // reduce + fp16 write: 3 heads x 96 uint2 (4 halves) = 288 items over 384 threads
    uint2* vout = (uint2*)(g_A + (size_t)par * BKA2);
    if (tid < 288) {
        int h = tid / 96, c = tid % 96;
        float4 r0 = part[h][0][c], r1 = part[h][1][c];
        float4 r2 = part[h][2][c], r3 = part[h][3][c];
        float rx = r0.x + r1.x + r2.x + r3.x;
        float ry = r0.y + r1.y + r2.y + r3.y;
        float rz = r0.z + r1.z + r2.z + r3.z;
        float rw = r0.w + r1.w + r2.w + r3.w;
        __half2 lo = __floats2half2_rn(rx, ry);
        __half2 hi = __floats2half2_rn(rz, rw);
        uint2 val;
        val.x = *(const uint32_t*)&lo;
        val.y = *(const uint32_t*)&hi;
        vout[((size_t)b * KA2 + h * Dd + half * 384) / 4 + c] = val;
    }
}

// ======================= driver (single stream, PDL launches, graph-safe) ===============
template <typename F, typename... Args>
static inline void launch_pdl(F f, dim3 grid, dim3 block, size_t smem, Args... args) {
    cudaLaunchConfig_t cfg = {};
    cfg.gridDim = grid;
    cfg.blockDim = block;
    cfg.dynamicSmemBytes = smem;
    cudaLaunchAttribute attr[1];
    attr[0].id = cudaLaunchAttributeProgrammaticStreamSerialization;
    attr[0].val.programmaticStreamSerializationAllowed = 1;
    cfg.attrs = attr;
    cfg.numAttrs = 1;
    cudaLaunchKernelEx(&cfg, f, args...);
}

extern "C" void kernel_launch(void* const* d_in, const int* in_sizes, int n_in,
                              void* d_out, int out_size) {
    (void)in_sizes; (void)n_in; (void)out_size;
    const float* x    = (const float*)d_in[0];
    const float* h0   = (const float*)d_in[1];
    const float* c0   = (const float*)d_in[2];
    const float* W1   = (const float*)d_in[3];
    const float* b1   = (const float*)d_in[4];
    const float* W2   = (const float*)d_in[5];
    const float* b2   = (const float*)d_in[6];
    const float* W3   = (const float*)d_in[7];
    const float* b3   = (const float*)d_in[8];
    const float* W_ih = (const float*)d_in[9];
    const float* W_hh = (const float*)d_in[10];
    const float* b_ih = (const float*)d_in[11];
    const float* b_hh = (const float*)d_in[12];
    float* out = (float*)d_out;

    cudaFuncSetAttribute(logits_kernel, cudaFuncAttributeMaxDynamicSharedMemorySize, SMEM1);
    cudaFuncSetAttribute(gates_kernel,  cudaFuncAttributeMaxDynamicSharedMemorySize, SMEM1);

    // 3 prep launches -> loop kernel at ncu capture index 5 is gates_kernel
    prep_wg_kernel<<<4096, 256>>>(W_ih, W_hh);
    prep_xwa_kernel<<<4096, 256>>>(x, W1, W2, W3);
    prep_init_kernel<<<1024, 256>>>(b_ih, b_hh, b1, b2, b3, h0, c0);

    for (int t = 0; t < Tt; t++) {
        const int par = t & 1;
        launch_pdl(logits_kernel, dim3(96),  dim3(128), SMEM1, par);
        launch_pdl(attnv_kernel,  dim3(512), dim3(384), 0,     par);
        launch_pdl(gates_kernel,  dim3(256), dim3(128), SMEM1, par);
        launch_pdl(lstm_kernel,   dim3(BH/256), dim3(256), 0,  out, t);
    }
}